// round 1
// baseline (speedup 1.0000x reference)
#include <cuda_runtime.h>
#include <math.h>

#define Lnum 2
#define Dm   1024
#define Hn   16
#define HDm  64
#define Vv   50257
#define Tn   2048
#define Bn   2
#define BT   (Bn*Tn)        // 4096
#define CDm  512
#define En   8
#define Fm   4096
#define EPSf 1e-5f

// ---------------- scratch (static device globals; no allocation) -------------
__device__ float g_x[BT*Dm];                 // 16 MB
__device__ float g_qkv[(size_t)BT*3*Dm];     // 48 MB
__device__ float g_attn[BT*Dm];              // 16 MB
__device__ float g_tmp[BT*Dm];               // 16 MB
__device__ float g_h[(size_t)BT*Fm];         // 64 MB
__device__ float g_moe[BT*Dm];               // 16 MB
__device__ float g_xf[BT*Dm];                // 16 MB
__device__ int   g_eidx[2];
__device__ float g_ew[2];

// ---------------- embed: x = embed_w[tok] + pos_w[t] -------------------------
__global__ void k_embed(const int* __restrict__ tokens,
                        const float* __restrict__ embed_w,
                        const float* __restrict__ pos_w)
{
    int row = blockIdx.x;            // b*T + t
    int t   = row % Tn;
    int tok = tokens[row];
    const float* e = embed_w + (long)tok * Dm;
    const float* p = pos_w   + (long)t   * Dm;
    float* x = g_x + (long)row * Dm;
    for (int d = threadIdx.x; d < Dm; d += blockDim.x)
        x[d] = e[d] + p[d];
}

// ---------------- generic GEMM: C[M,N] = op(A[M,K] @ W[N,K]^T + bias) --------
// flags: 1 = GELU(exact), 2 = accumulate into C, 4 = expert-indexed W/bias
//        8 = scale by g_ew[slot]
__global__ void k_gemm(const float* __restrict__ A,
                       const float* __restrict__ Wb,
                       const float* __restrict__ Bb,
                       float* __restrict__ C,
                       int M, int N, int K,
                       long wstride, long bstride,
                       int slot, int flags)
{
    __shared__ float As[16][64];
    __shared__ float Bs[16][64];

    const float* W    = Wb;
    const float* bias = Bb;
    if (flags & 4) {
        int e = g_eidx[slot];
        W += (long)e * wstride;
        if (bias) bias += (long)e * bstride;
    }
    float alpha = (flags & 8) ? g_ew[slot] : 1.0f;

    int bm = blockIdx.y * 64, bn = blockIdx.x * 64;
    int tid = threadIdx.x;
    int tx = tid & 15, ty = tid >> 4;

    float acc[4][4] = {};

    for (int k0 = 0; k0 < K; k0 += 16) {
        #pragma unroll
        for (int i = tid; i < 1024; i += 256) {
            int r = i >> 4, c = i & 15;
            int am = bm + r;
            As[c][r] = (am < M) ? A[(long)am * K + k0 + c] : 0.f;
            int wn = bn + r;
            Bs[c][r] = (wn < N) ? W[(long)wn * K + k0 + c] : 0.f;
        }
        __syncthreads();
        #pragma unroll
        for (int kk = 0; kk < 16; kk++) {
            float4 a4 = *(const float4*)&As[kk][ty * 4];
            float4 b4 = *(const float4*)&Bs[kk][tx * 4];
            float ra[4] = {a4.x, a4.y, a4.z, a4.w};
            float rb[4] = {b4.x, b4.y, b4.z, b4.w};
            #pragma unroll
            for (int i = 0; i < 4; i++)
                #pragma unroll
                for (int j = 0; j < 4; j++)
                    acc[i][j] += ra[i] * rb[j];
        }
        __syncthreads();
    }

    #pragma unroll
    for (int i = 0; i < 4; i++) {
        int m = bm + ty * 4 + i;
        if (m >= M) continue;
        #pragma unroll
        for (int j = 0; j < 4; j++) {
            int n = bn + tx * 4 + j;
            if (n >= N) continue;
            float v = acc[i][j];
            if (bias) v += bias[n];
            if (flags & 1) v = 0.5f * v * (1.0f + erff(v * 0.70710678118654752f));
            v *= alpha;
            long o = (long)m * N + n;
            if (flags & 2) C[o] += v; else C[o] = v;
        }
    }
}

// ---------------- causal attention, block per (q, h, b) ----------------------
__global__ void k_attn()
{
    int t = blockIdx.x, h = blockIdx.y, b = blockIdx.z;
    int tid = threadIdx.x;
    int nk = t + 1;

    __shared__ float sq[HDm];
    __shared__ float sp[Tn];
    __shared__ float red[128];
    __shared__ float oacc[128];

    const long base = (long)(b * Tn) * (3 * Dm);
    const float* qrow = g_qkv + base + (long)t * (3 * Dm) + h * HDm;
    if (tid < HDm) sq[tid] = qrow[tid];
    __syncthreads();

    // scores
    for (int j = tid; j < nk; j += 128) {
        const float* krow = g_qkv + base + (long)j * (3 * Dm) + Dm + h * HDm;
        float s = 0.f;
        #pragma unroll
        for (int d = 0; d < HDm; d++) s += sq[d] * krow[d];
        sp[j] = s * 0.125f;
    }
    __syncthreads();

    // max
    float m = -3.4e38f;
    for (int j = tid; j < nk; j += 128) m = fmaxf(m, sp[j]);
    red[tid] = m; __syncthreads();
    for (int s = 64; s > 0; s >>= 1) {
        if (tid < s) red[tid] = fmaxf(red[tid], red[tid + s]);
        __syncthreads();
    }
    m = red[0]; __syncthreads();

    // exp + sum
    float sum = 0.f;
    for (int j = tid; j < nk; j += 128) {
        float e = expf(sp[j] - m);
        sp[j] = e;
        sum += e;
    }
    red[tid] = sum; __syncthreads();
    for (int s = 64; s > 0; s >>= 1) {
        if (tid < s) red[tid] += red[tid + s];
        __syncthreads();
    }
    float inv = 1.0f / red[0]; __syncthreads();

    // weighted V: thread d = tid&63, split j range in halves
    int d = tid & 63, half = tid >> 6;
    float acc = 0.f;
    for (int j = half; j < nk; j += 2)
        acc += sp[j] * g_qkv[base + (long)j * (3 * Dm) + 2 * Dm + h * HDm + d];
    oacc[tid] = acc; __syncthreads();
    if (tid < 64) {
        float o = (oacc[tid] + oacc[tid + 64]) * inv;
        g_attn[(long)(b * Tn + t) * Dm + h * HDm + tid] = o;
    }
}

// ---------------- residual add + LayerNorm (y may be null) -------------------
__global__ void k_add_ln(const float* __restrict__ x,
                         const float* __restrict__ y,
                         const float* __restrict__ g,
                         const float* __restrict__ bta,
                         float* __restrict__ out)
{
    int row = blockIdx.x;
    int tid = threadIdx.x;
    __shared__ float buf[Dm];
    __shared__ float red[256];

    float psum = 0.f;
    for (int i = tid; i < Dm; i += 256) {
        float v = x[(long)row * Dm + i];
        if (y) v += y[(long)row * Dm + i];
        buf[i] = v;
        psum += v;
    }
    red[tid] = psum; __syncthreads();
    for (int s = 128; s > 0; s >>= 1) {
        if (tid < s) red[tid] += red[tid + s];
        __syncthreads();
    }
    float mu = red[0] * (1.0f / Dm); __syncthreads();

    float pvar = 0.f;
    for (int i = tid; i < Dm; i += 256) {
        float dv = buf[i] - mu;
        pvar += dv * dv;
    }
    red[tid] = pvar; __syncthreads();
    for (int s = 128; s > 0; s >>= 1) {
        if (tid < s) red[tid] += red[tid + s];
        __syncthreads();
    }
    float rstd = rsqrtf(red[0] * (1.0f / Dm) + EPSf); __syncthreads();

    for (int i = tid; i < Dm; i += 256)
        out[(long)row * Dm + i] = (buf[i] - mu) * rstd * g[i] + bta[i];
}

// ---------------- router: top-2 over softmax(router_w @ mean(c_states)) ------
__global__ void k_router(const float* __restrict__ c_states,
                         const float* __restrict__ rw,
                         const float* __restrict__ rb)
{
    int tid = threadIdx.x;
    __shared__ float cm[CDm];
    __shared__ float lg[En];

    for (int d = tid; d < CDm; d += 256) {
        float s = 0.f;
        for (int r = 0; r < 64; r++) s += c_states[(long)r * CDm + d];
        cm[d] = s * (1.0f / 64.0f);
    }
    __syncthreads();
    if (tid < En) {
        float s = 0.f;
        const float* w = rw + (long)tid * CDm;
        for (int d = 0; d < CDm; d++) s += w[d] * cm[d];
        lg[tid] = s + rb[tid];
    }
    __syncthreads();
    if (tid == 0) {
        float mx = lg[0];
        for (int e = 1; e < En; e++) mx = fmaxf(mx, lg[e]);
        float p[En], sum = 0.f;
        for (int e = 0; e < En; e++) { p[e] = expf(lg[e] - mx); sum += p[e]; }
        for (int e = 0; e < En; e++) p[e] /= sum;
        int i0 = 0;
        for (int e = 1; e < En; e++) if (p[e] > p[i0]) i0 = e;
        int i1 = (i0 == 0) ? 1 : 0;
        for (int e = 0; e < En; e++) if (e != i0 && p[e] > p[i1]) i1 = e;
        float ws = p[i0] + p[i1];
        g_eidx[0] = i0; g_eidx[1] = i1;
        g_ew[0] = p[i0] / ws; g_ew[1] = p[i1] / ws;
    }
}

// ============================================================================
extern "C" void kernel_launch(void* const* d_in, const int* in_sizes, int n_in,
                              void* d_out, int out_size)
{
    const int*   tokens   = (const int*)  d_in[0];
    const float* c_states = (const float*)d_in[1];
    const float* embed_w  = (const float*)d_in[2];
    const float* pos_w    = (const float*)d_in[3];
    const float* in_w     = (const float*)d_in[4];
    const float* in_b     = (const float*)d_in[5];
    const float* out_w    = (const float*)d_in[6];
    const float* out_b    = (const float*)d_in[7];
    const float* ln_a_g   = (const float*)d_in[8];
    const float* ln_a_b   = (const float*)d_in[9];
    const float* router_w = (const float*)d_in[10];
    const float* router_b = (const float*)d_in[11];
    const float* e_w1     = (const float*)d_in[12];
    const float* e_b1     = (const float*)d_in[13];
    const float* e_w2     = (const float*)d_in[14];
    const float* e_b2     = (const float*)d_in[15];
    const float* ln_m_g   = (const float*)d_in[16];
    const float* ln_m_b   = (const float*)d_in[17];
    const float* ln_f_g   = (const float*)d_in[18];
    const float* ln_f_b   = (const float*)d_in[19];
    const float* head_w   = (const float*)d_in[20];
    float* out = (float*)d_out;

    float *p_x, *p_qkv, *p_attn, *p_tmp, *p_h, *p_moe, *p_xf;
    cudaGetSymbolAddress((void**)&p_x,    g_x);
    cudaGetSymbolAddress((void**)&p_qkv,  g_qkv);
    cudaGetSymbolAddress((void**)&p_attn, g_attn);
    cudaGetSymbolAddress((void**)&p_tmp,  g_tmp);
    cudaGetSymbolAddress((void**)&p_h,    g_h);
    cudaGetSymbolAddress((void**)&p_moe,  g_moe);
    cudaGetSymbolAddress((void**)&p_xf,   g_xf);

    dim3 blk(256);

    k_embed<<<BT, 256>>>(tokens, embed_w, pos_w);

    for (int l = 0; l < Lnum; l++) {
        // QKV projection
        {
            dim3 grid((3 * Dm) / 64, BT / 64);
            k_gemm<<<grid, blk>>>(p_x, in_w + (long)l * 3 * Dm * Dm,
                                  in_b + (long)l * 3 * Dm, p_qkv,
                                  BT, 3 * Dm, Dm, 0, 0, 0, 0);
        }
        // attention
        {
            dim3 grid(Tn, Hn, Bn);
            k_attn<<<grid, 128>>>();
        }
        // output projection
        {
            dim3 grid(Dm / 64, BT / 64);
            k_gemm<<<grid, blk>>>(p_attn, out_w + (long)l * Dm * Dm,
                                  out_b + (long)l * Dm, p_tmp,
                                  BT, Dm, Dm, 0, 0, 0, 0);
        }
        // x = LN(x + attn_out)
        k_add_ln<<<BT, 256>>>(p_x, p_tmp, ln_a_g + l * Dm, ln_a_b + l * Dm, p_x);

        // router (global top-2 from c_states)
        k_router<<<1, 256>>>(c_states, router_w + (long)l * En * CDm,
                             router_b + (long)l * En);

        // MoE: two experts, sequential; second accumulates
        for (int slot = 0; slot < 2; slot++) {
            {
                dim3 grid(Fm / 64, BT / 64);
                k_gemm<<<grid, blk>>>(p_x,
                                      e_w1 + (long)l * En * Fm * Dm,
                                      e_b1 + (long)l * En * Fm,
                                      p_h, BT, Fm, Dm,
                                      (long)Fm * Dm, (long)Fm,
                                      slot, /*gelu+expert*/ 1 | 4);
            }
            {
                dim3 grid(Dm / 64, BT / 64);
                int flags = 4 | 8 | (slot == 1 ? 2 : 0);   // expert + scale (+accum)
                k_gemm<<<grid, blk>>>(p_h,
                                      e_w2 + (long)l * En * Dm * Fm,
                                      e_b2 + (long)l * En * Dm,
                                      p_moe, BT, Dm, Fm,
                                      (long)Dm * Fm, (long)Dm,
                                      slot, flags);
            }
        }
        // x = LN(x + moe_out)
        k_add_ln<<<BT, 256>>>(p_x, p_moe, ln_m_g + l * Dm, ln_m_b + l * Dm, p_x);
    }

    // final LN
    k_add_ln<<<BT, 256>>>(p_x, nullptr, ln_f_g, ln_f_b, p_xf);

    // LM head: out[BT, V] = xf @ head_w^T
    {
        dim3 grid((Vv + 63) / 64, BT / 64);
        k_gemm<<<grid, blk>>>(p_xf, head_w, nullptr, out,
                              BT, Vv, Dm, 0, 0, 0, 0);
    }
}

// round 2
// speedup vs baseline: 1.8754x; 1.8754x over previous
#include <cuda_runtime.h>
#include <cuda_bf16.h>
#include <math.h>

#define Lnum 2
#define Dm   1024
#define Hn   16
#define HDm  64
#define Vv   50257
#define Tn   2048
#define Bn   2
#define BT   (Bn*Tn)        // 4096
#define CDm  512
#define En   8
#define Fm   4096
#define EPSf 1e-5f

// GEMM tiling
#define BM 128
#define BN 128
#define BK 32
#define SST 40              // smem row stride (halves) — conflict-free frag loads

// ---------------- scratch (static device globals; no allocation) -------------
__device__ float g_x[BT*Dm];
__device__ float g_qkv[(size_t)BT*3*Dm];
__device__ float g_attn[BT*Dm];
__device__ float g_tmp[BT*Dm];
__device__ float g_h[(size_t)BT*Fm];
__device__ float g_moe[BT*Dm];
__device__ float g_xf[BT*Dm];
__device__ int   g_eidx[2];
__device__ float g_ew[2];

// ---------------- embed ------------------------------------------------------
__global__ void k_embed(const int* __restrict__ tokens,
                        const float* __restrict__ embed_w,
                        const float* __restrict__ pos_w)
{
    int row = blockIdx.x;
    int t   = row % Tn;
    int tok = tokens[row];
    const float* e = embed_w + (long)tok * Dm;
    const float* p = pos_w   + (long)t   * Dm;
    float* x = g_x + (long)row * Dm;
    for (int d = threadIdx.x; d < Dm; d += blockDim.x)
        x[d] = e[d] + p[d];
}

// ---------------- bf16 split helper ------------------------------------------
__device__ __forceinline__ void bsplit(float v, __nv_bfloat16& hi, __nv_bfloat16& lo)
{
    hi = __float2bfloat16(v);
    lo = __float2bfloat16(v - __bfloat162float(hi));
}

#define MMA16816(d, a, b) \
    asm volatile("mma.sync.aligned.m16n8k16.row.col.f32.bf16.bf16.f32 " \
                 "{%0,%1,%2,%3},{%4,%5,%6,%7},{%8,%9},{%0,%1,%2,%3};\n" \
                 : "+f"(d[0]), "+f"(d[1]), "+f"(d[2]), "+f"(d[3])       \
                 : "r"(a[0]), "r"(a[1]), "r"(a[2]), "r"(a[3]),          \
                   "r"(b[0]), "r"(b[1]))

// ---------------- tensor-core GEMM: C[M,N] = op(A[M,K] @ W[N,K]^T + bias) ----
// bf16 2-term split (3 MMAs) for fp32-grade accuracy.
// flags: 1=GELU, 2=accumulate, 4=expert-indexed W/bias, 8=scale by g_ew[slot]
__global__ void __launch_bounds__(256, 2)
k_gemm(const float* __restrict__ A,
       const float* __restrict__ Wb,
       const float* __restrict__ Bb,
       float* __restrict__ C,
       int M, int N, int K,
       long wstride, long bstride,
       int slot, int flags)
{
    __shared__ __nv_bfloat16 As_h[BM*SST];
    __shared__ __nv_bfloat16 As_l[BM*SST];
    __shared__ __nv_bfloat16 Bs_h[BN*SST];
    __shared__ __nv_bfloat16 Bs_l[BN*SST];

    const float* W    = Wb;
    const float* bias = Bb;
    if (flags & 4) {
        int e = g_eidx[slot];
        W += (long)e * wstride;
        if (bias) bias += (long)e * bstride;
    }
    float alpha = (flags & 8) ? g_ew[slot] : 1.0f;

    const int bm = blockIdx.y * BM, bn = blockIdx.x * BN;
    const int tid  = threadIdx.x;
    const int lane = tid & 31, warp = tid >> 5;
    const int wm = warp & 1;       // 2 warps along M (64 rows each)
    const int wn = warp >> 1;      // 4 warps along N (32 cols each)
    const int g  = lane >> 2;
    const int t2 = (lane & 3) * 2;

    float acc[4][4][4] = {};       // [mf][nf][c0..c3]

    for (int k0 = 0; k0 < K; k0 += BK) {
        // ---- stage A tile (128 x 32) fp32 -> bf16 hi/lo ----
        #pragma unroll
        for (int i = 0; i < 4; i++) {
            int idx = tid + i * 256;            // 0..1023 float4s
            int r = idx >> 3, q = (idx & 7) * 4;
            float4 v = *(const float4*)&A[(long)(bm + r) * K + k0 + q];
            __nv_bfloat16 h0,l0,h1,l1,h2,l2,h3,l3;
            bsplit(v.x,h0,l0); bsplit(v.y,h1,l1);
            bsplit(v.z,h2,l2); bsplit(v.w,h3,l3);
            int off = r * SST + q;
            *(__nv_bfloat162*)&As_h[off]   = __halves2bfloat162(h0,h1);
            *(__nv_bfloat162*)&As_h[off+2] = __halves2bfloat162(h2,h3);
            *(__nv_bfloat162*)&As_l[off]   = __halves2bfloat162(l0,l1);
            *(__nv_bfloat162*)&As_l[off+2] = __halves2bfloat162(l2,l3);
        }
        // ---- stage W tile (128 x 32), guard N ----
        #pragma unroll
        for (int i = 0; i < 4; i++) {
            int idx = tid + i * 256;
            int r = idx >> 3, q = (idx & 7) * 4;
            int nrow = bn + r;
            float4 v = make_float4(0.f, 0.f, 0.f, 0.f);
            if (nrow < N) v = *(const float4*)&W[(long)nrow * K + k0 + q];
            __nv_bfloat16 h0,l0,h1,l1,h2,l2,h3,l3;
            bsplit(v.x,h0,l0); bsplit(v.y,h1,l1);
            bsplit(v.z,h2,l2); bsplit(v.w,h3,l3);
            int off = r * SST + q;
            *(__nv_bfloat162*)&Bs_h[off]   = __halves2bfloat162(h0,h1);
            *(__nv_bfloat162*)&Bs_h[off+2] = __halves2bfloat162(h2,h3);
            *(__nv_bfloat162*)&Bs_l[off]   = __halves2bfloat162(l0,l1);
            *(__nv_bfloat162*)&Bs_l[off+2] = __halves2bfloat162(l2,l3);
        }
        __syncthreads();

        // ---- compute: 2 x k16 steps ----
        #pragma unroll
        for (int kk = 0; kk < BK; kk += 16) {
            unsigned ah[4][4], al[4][4], bh[4][2], bl[4][2];
            #pragma unroll
            for (int mf = 0; mf < 4; mf++) {
                int r0 = (wm * 64 + mf * 16 + g) * SST + kk + t2;
                ah[mf][0] = *(const unsigned*)&As_h[r0];
                ah[mf][1] = *(const unsigned*)&As_h[r0 + 8*SST];
                ah[mf][2] = *(const unsigned*)&As_h[r0 + 8];
                ah[mf][3] = *(const unsigned*)&As_h[r0 + 8*SST + 8];
                al[mf][0] = *(const unsigned*)&As_l[r0];
                al[mf][1] = *(const unsigned*)&As_l[r0 + 8*SST];
                al[mf][2] = *(const unsigned*)&As_l[r0 + 8];
                al[mf][3] = *(const unsigned*)&As_l[r0 + 8*SST + 8];
            }
            #pragma unroll
            for (int nf = 0; nf < 4; nf++) {
                int c0 = (wn * 32 + nf * 8 + g) * SST + kk + t2;
                bh[nf][0] = *(const unsigned*)&Bs_h[c0];
                bh[nf][1] = *(const unsigned*)&Bs_h[c0 + 8];
                bl[nf][0] = *(const unsigned*)&Bs_l[c0];
                bl[nf][1] = *(const unsigned*)&Bs_l[c0 + 8];
            }
            #pragma unroll
            for (int mf = 0; mf < 4; mf++)
                #pragma unroll
                for (int nf = 0; nf < 4; nf++) {
                    MMA16816(acc[mf][nf], ah[mf], bh[nf]);
                    MMA16816(acc[mf][nf], ah[mf], bl[nf]);
                    MMA16816(acc[mf][nf], al[mf], bh[nf]);
                }
        }
        __syncthreads();
    }

    // ---- epilogue ----
    #pragma unroll
    for (int mf = 0; mf < 4; mf++) {
        int m0 = bm + wm * 64 + mf * 16 + g;
        #pragma unroll
        for (int nf = 0; nf < 4; nf++) {
            int n0 = bn + wn * 32 + nf * 8 + t2;
            #pragma unroll
            for (int c = 0; c < 4; c++) {
                int m = m0 + (c >> 1) * 8;
                int n = n0 + (c & 1);
                if (n >= N) continue;
                float v = acc[mf][nf][c];
                if (bias) v += bias[n];
                if (flags & 1) v = 0.5f * v * (1.0f + erff(v * 0.70710678118654752f));
                v *= alpha;
                long o = (long)m * N + n;
                if (flags & 2) C[o] += v; else C[o] = v;
            }
        }
    }
}

// ---------------- causal attention, block per (q, h, b) ----------------------
__global__ void k_attn()
{
    int t = blockIdx.x, h = blockIdx.y, b = blockIdx.z;
    int tid = threadIdx.x;
    int nk = t + 1;

    __shared__ float sq[HDm];
    __shared__ float sp[Tn];
    __shared__ float red[128];
    __shared__ float oacc[128];

    const long base = (long)(b * Tn) * (3 * Dm);
    const float* qrow = g_qkv + base + (long)t * (3 * Dm) + h * HDm;
    if (tid < HDm) sq[tid] = qrow[tid];
    __syncthreads();

    for (int j = tid; j < nk; j += 128) {
        const float* krow = g_qkv + base + (long)j * (3 * Dm) + Dm + h * HDm;
        float s = 0.f;
        #pragma unroll
        for (int d = 0; d < HDm; d++) s += sq[d] * krow[d];
        sp[j] = s * 0.125f;
    }
    __syncthreads();

    float m = -3.4e38f;
    for (int j = tid; j < nk; j += 128) m = fmaxf(m, sp[j]);
    red[tid] = m; __syncthreads();
    for (int s = 64; s > 0; s >>= 1) {
        if (tid < s) red[tid] = fmaxf(red[tid], red[tid + s]);
        __syncthreads();
    }
    m = red[0]; __syncthreads();

    float sum = 0.f;
    for (int j = tid; j < nk; j += 128) {
        float e = expf(sp[j] - m);
        sp[j] = e;
        sum += e;
    }
    red[tid] = sum; __syncthreads();
    for (int s = 64; s > 0; s >>= 1) {
        if (tid < s) red[tid] += red[tid + s];
        __syncthreads();
    }
    float inv = 1.0f / red[0]; __syncthreads();

    int d = tid & 63, half = tid >> 6;
    float acc = 0.f;
    for (int j = half; j < nk; j += 2)
        acc += sp[j] * g_qkv[base + (long)j * (3 * Dm) + 2 * Dm + h * HDm + d];
    oacc[tid] = acc; __syncthreads();
    if (tid < 64) {
        float o = (oacc[tid] + oacc[tid + 64]) * inv;
        g_attn[(long)(b * Tn + t) * Dm + h * HDm + tid] = o;
    }
}

// ---------------- residual add + LayerNorm -----------------------------------
__global__ void k_add_ln(const float* __restrict__ x,
                         const float* __restrict__ y,
                         const float* __restrict__ g,
                         const float* __restrict__ bta,
                         float* __restrict__ out)
{
    int row = blockIdx.x;
    int tid = threadIdx.x;
    __shared__ float buf[Dm];
    __shared__ float red[256];

    float psum = 0.f;
    for (int i = tid; i < Dm; i += 256) {
        float v = x[(long)row * Dm + i];
        if (y) v += y[(long)row * Dm + i];
        buf[i] = v;
        psum += v;
    }
    red[tid] = psum; __syncthreads();
    for (int s = 128; s > 0; s >>= 1) {
        if (tid < s) red[tid] += red[tid + s];
        __syncthreads();
    }
    float mu = red[0] * (1.0f / Dm); __syncthreads();

    float pvar = 0.f;
    for (int i = tid; i < Dm; i += 256) {
        float dv = buf[i] - mu;
        pvar += dv * dv;
    }
    red[tid] = pvar; __syncthreads();
    for (int s = 128; s > 0; s >>= 1) {
        if (tid < s) red[tid] += red[tid + s];
        __syncthreads();
    }
    float rstd = rsqrtf(red[0] * (1.0f / Dm) + EPSf); __syncthreads();

    for (int i = tid; i < Dm; i += 256)
        out[(long)row * Dm + i] = (buf[i] - mu) * rstd * g[i] + bta[i];
}

// ---------------- router ------------------------------------------------------
__global__ void k_router(const float* __restrict__ c_states,
                         const float* __restrict__ rw,
                         const float* __restrict__ rb)
{
    int tid = threadIdx.x;
    __shared__ float cm[CDm];
    __shared__ float lg[En];

    for (int d = tid; d < CDm; d += 256) {
        float s = 0.f;
        for (int r = 0; r < 64; r++) s += c_states[(long)r * CDm + d];
        cm[d] = s * (1.0f / 64.0f);
    }
    __syncthreads();
    if (tid < En) {
        float s = 0.f;
        const float* w = rw + (long)tid * CDm;
        for (int d = 0; d < CDm; d++) s += w[d] * cm[d];
        lg[tid] = s + rb[tid];
    }
    __syncthreads();
    if (tid == 0) {
        float mx = lg[0];
        for (int e = 1; e < En; e++) mx = fmaxf(mx, lg[e]);
        float p[En], sum = 0.f;
        for (int e = 0; e < En; e++) { p[e] = expf(lg[e] - mx); sum += p[e]; }
        for (int e = 0; e < En; e++) p[e] /= sum;
        int i0 = 0;
        for (int e = 1; e < En; e++) if (p[e] > p[i0]) i0 = e;
        int i1 = (i0 == 0) ? 1 : 0;
        for (int e = 0; e < En; e++) if (e != i0 && p[e] > p[i1]) i1 = e;
        float ws = p[i0] + p[i1];
        g_eidx[0] = i0; g_eidx[1] = i1;
        g_ew[0] = p[i0] / ws; g_ew[1] = p[i1] / ws;
    }
}

// ============================================================================
extern "C" void kernel_launch(void* const* d_in, const int* in_sizes, int n_in,
                              void* d_out, int out_size)
{
    const int*   tokens   = (const int*)  d_in[0];
    const float* c_states = (const float*)d_in[1];
    const float* embed_w  = (const float*)d_in[2];
    const float* pos_w    = (const float*)d_in[3];
    const float* in_w     = (const float*)d_in[4];
    const float* in_b     = (const float*)d_in[5];
    const float* out_w    = (const float*)d_in[6];
    const float* out_b    = (const float*)d_in[7];
    const float* ln_a_g   = (const float*)d_in[8];
    const float* ln_a_b   = (const float*)d_in[9];
    const float* router_w = (const float*)d_in[10];
    const float* router_b = (const float*)d_in[11];
    const float* e_w1     = (const float*)d_in[12];
    const float* e_b1     = (const float*)d_in[13];
    const float* e_w2     = (const float*)d_in[14];
    const float* e_b2     = (const float*)d_in[15];
    const float* ln_m_g   = (const float*)d_in[16];
    const float* ln_m_b   = (const float*)d_in[17];
    const float* ln_f_g   = (const float*)d_in[18];
    const float* ln_f_b   = (const float*)d_in[19];
    const float* head_w   = (const float*)d_in[20];
    float* out = (float*)d_out;

    float *p_x, *p_qkv, *p_attn, *p_tmp, *p_h, *p_moe, *p_xf;
    cudaGetSymbolAddress((void**)&p_x,    g_x);
    cudaGetSymbolAddress((void**)&p_qkv,  g_qkv);
    cudaGetSymbolAddress((void**)&p_attn, g_attn);
    cudaGetSymbolAddress((void**)&p_tmp,  g_tmp);
    cudaGetSymbolAddress((void**)&p_h,    g_h);
    cudaGetSymbolAddress((void**)&p_moe,  g_moe);
    cudaGetSymbolAddress((void**)&p_xf,   g_xf);

    dim3 blk(256);

    k_embed<<<BT, 256>>>(tokens, embed_w, pos_w);

    for (int l = 0; l < Lnum; l++) {
        {   // QKV projection
            dim3 grid((3 * Dm) / BN, BT / BM);
            k_gemm<<<grid, blk>>>(p_x, in_w + (long)l * 3 * Dm * Dm,
                                  in_b + (long)l * 3 * Dm, p_qkv,
                                  BT, 3 * Dm, Dm, 0, 0, 0, 0);
        }
        {   // attention
            dim3 grid(Tn, Hn, Bn);
            k_attn<<<grid, 128>>>();
        }
        {   // output projection
            dim3 grid(Dm / BN, BT / BM);
            k_gemm<<<grid, blk>>>(p_attn, out_w + (long)l * Dm * Dm,
                                  out_b + (long)l * Dm, p_tmp,
                                  BT, Dm, Dm, 0, 0, 0, 0);
        }
        k_add_ln<<<BT, 256>>>(p_x, p_tmp, ln_a_g + l * Dm, ln_a_b + l * Dm, p_x);

        k_router<<<1, 256>>>(c_states, router_w + (long)l * En * CDm,
                             router_b + (long)l * En);

        for (int slot = 0; slot < 2; slot++) {
            {
                dim3 grid(Fm / BN, BT / BM);
                k_gemm<<<grid, blk>>>(p_x,
                                      e_w1 + (long)l * En * Fm * Dm,
                                      e_b1 + (long)l * En * Fm,
                                      p_h, BT, Fm, Dm,
                                      (long)Fm * Dm, (long)Fm,
                                      slot, 1 | 4);
            }
            {
                dim3 grid(Dm / BN, BT / BM);
                int flags = 4 | 8 | (slot == 1 ? 2 : 0);
                k_gemm<<<grid, blk>>>(p_h,
                                      e_w2 + (long)l * En * Dm * Fm,
                                      e_b2 + (long)l * En * Dm,
                                      p_moe, BT, Dm, Fm,
                                      (long)Dm * Fm, (long)Dm,
                                      slot, flags);
            }
        }
        k_add_ln<<<BT, 256>>>(p_x, p_moe, ln_m_g + l * Dm, ln_m_b + l * Dm, p_x);
    }

    k_add_ln<<<BT, 256>>>(p_x, nullptr, ln_f_g, ln_f_b, p_xf);

    {   // LM head
        dim3 grid((Vv + BN - 1) / BN, BT / BM);
        k_gemm<<<grid, blk>>>(p_xf, head_w, nullptr, out,
                              BT, Vv, Dm, 0, 0, 0, 0);
    }
}

// round 3
// speedup vs baseline: 7.7451x; 4.1298x over previous
#include <cuda_runtime.h>
#include <cuda_bf16.h>
#include <math.h>

#define Lnum 2
#define Dm   1024
#define Hn   16
#define HDm  64
#define Vv   50257
#define Tn   2048
#define Bn   2
#define BT   (Bn*Tn)        // 4096
#define CDm  512
#define En   8
#define Fm   4096
#define EPSf 1e-5f

// GEMM tiling
#define BM 128
#define BN 128
#define BK 32
#define SST 40              // gemm smem row stride (halves)

// attention tiling
#define AQT 64              // queries per block
#define AKT 64              // keys per tile
#define AST 72              // attn smem row stride (halves)

// ---------------- scratch (static device globals; no allocation) -------------
__device__ float g_x[BT*Dm];
__device__ float g_qkv[(size_t)BT*3*Dm];
__device__ float g_attn[BT*Dm];
__device__ float g_tmp[BT*Dm];
__device__ float g_h[(size_t)BT*Fm];
__device__ float g_moe[BT*Dm];
__device__ float g_xf[BT*Dm];
__device__ int   g_eidx[2];
__device__ float g_ew[2];

// ---------------- embed ------------------------------------------------------
__global__ void k_embed(const int* __restrict__ tokens,
                        const float* __restrict__ embed_w,
                        const float* __restrict__ pos_w)
{
    int row = blockIdx.x;
    int t   = row % Tn;
    int tok = tokens[row];
    const float* e = embed_w + (long)tok * Dm;
    const float* p = pos_w   + (long)t   * Dm;
    float* x = g_x + (long)row * Dm;
    for (int d = threadIdx.x; d < Dm; d += blockDim.x)
        x[d] = e[d] + p[d];
}

// ---------------- bf16 split helper ------------------------------------------
__device__ __forceinline__ void bsplit(float v, __nv_bfloat16& hi, __nv_bfloat16& lo)
{
    hi = __float2bfloat16(v);
    lo = __float2bfloat16(v - __bfloat162float(hi));
}
__device__ __forceinline__ unsigned pack2(float a, float b)
{
    __nv_bfloat162 t = __halves2bfloat162(__float2bfloat16(a), __float2bfloat16(b));
    return *(unsigned*)&t;
}
__device__ __forceinline__ unsigned pack2lo(float a, float ah, float b, float bh)
{
    __nv_bfloat162 t = __halves2bfloat162(__float2bfloat16(a - ah),
                                          __float2bfloat16(b - bh));
    return *(unsigned*)&t;
}

#define MMA16816(d, a, b) \
    asm volatile("mma.sync.aligned.m16n8k16.row.col.f32.bf16.bf16.f32 " \
                 "{%0,%1,%2,%3},{%4,%5,%6,%7},{%8,%9},{%0,%1,%2,%3};\n" \
                 : "+f"(d[0]), "+f"(d[1]), "+f"(d[2]), "+f"(d[3])       \
                 : "r"(a[0]), "r"(a[1]), "r"(a[2]), "r"(a[3]),          \
                   "r"(b[0]), "r"(b[1]))

// ---------------- tensor-core GEMM (unchanged from R1) -----------------------
__global__ void __launch_bounds__(256, 2)
k_gemm(const float* __restrict__ A,
       const float* __restrict__ Wb,
       const float* __restrict__ Bb,
       float* __restrict__ C,
       int M, int N, int K,
       long wstride, long bstride,
       int slot, int flags)
{
    __shared__ __nv_bfloat16 As_h[BM*SST];
    __shared__ __nv_bfloat16 As_l[BM*SST];
    __shared__ __nv_bfloat16 Bs_h[BN*SST];
    __shared__ __nv_bfloat16 Bs_l[BN*SST];

    const float* W    = Wb;
    const float* bias = Bb;
    if (flags & 4) {
        int e = g_eidx[slot];
        W += (long)e * wstride;
        if (bias) bias += (long)e * bstride;
    }
    float alpha = (flags & 8) ? g_ew[slot] : 1.0f;

    const int bm = blockIdx.y * BM, bn = blockIdx.x * BN;
    const int tid  = threadIdx.x;
    const int lane = tid & 31, warp = tid >> 5;
    const int wm = warp & 1;
    const int wn = warp >> 1;
    const int g  = lane >> 2;
    const int t2 = (lane & 3) * 2;

    float acc[4][4][4] = {};

    for (int k0 = 0; k0 < K; k0 += BK) {
        #pragma unroll
        for (int i = 0; i < 4; i++) {
            int idx = tid + i * 256;
            int r = idx >> 3, q = (idx & 7) * 4;
            float4 v = *(const float4*)&A[(long)(bm + r) * K + k0 + q];
            __nv_bfloat16 h0,l0,h1,l1,h2,l2,h3,l3;
            bsplit(v.x,h0,l0); bsplit(v.y,h1,l1);
            bsplit(v.z,h2,l2); bsplit(v.w,h3,l3);
            int off = r * SST + q;
            *(__nv_bfloat162*)&As_h[off]   = __halves2bfloat162(h0,h1);
            *(__nv_bfloat162*)&As_h[off+2] = __halves2bfloat162(h2,h3);
            *(__nv_bfloat162*)&As_l[off]   = __halves2bfloat162(l0,l1);
            *(__nv_bfloat162*)&As_l[off+2] = __halves2bfloat162(l2,l3);
        }
        #pragma unroll
        for (int i = 0; i < 4; i++) {
            int idx = tid + i * 256;
            int r = idx >> 3, q = (idx & 7) * 4;
            int nrow = bn + r;
            float4 v = make_float4(0.f, 0.f, 0.f, 0.f);
            if (nrow < N) v = *(const float4*)&W[(long)nrow * K + k0 + q];
            __nv_bfloat16 h0,l0,h1,l1,h2,l2,h3,l3;
            bsplit(v.x,h0,l0); bsplit(v.y,h1,l1);
            bsplit(v.z,h2,l2); bsplit(v.w,h3,l3);
            int off = r * SST + q;
            *(__nv_bfloat162*)&Bs_h[off]   = __halves2bfloat162(h0,h1);
            *(__nv_bfloat162*)&Bs_h[off+2] = __halves2bfloat162(h2,h3);
            *(__nv_bfloat162*)&Bs_l[off]   = __halves2bfloat162(l0,l1);
            *(__nv_bfloat162*)&Bs_l[off+2] = __halves2bfloat162(l2,l3);
        }
        __syncthreads();

        #pragma unroll
        for (int kk = 0; kk < BK; kk += 16) {
            unsigned ah[4][4], al[4][4], bh[4][2], bl[4][2];
            #pragma unroll
            for (int mf = 0; mf < 4; mf++) {
                int r0 = (wm * 64 + mf * 16 + g) * SST + kk + t2;
                ah[mf][0] = *(const unsigned*)&As_h[r0];
                ah[mf][1] = *(const unsigned*)&As_h[r0 + 8*SST];
                ah[mf][2] = *(const unsigned*)&As_h[r0 + 8];
                ah[mf][3] = *(const unsigned*)&As_h[r0 + 8*SST + 8];
                al[mf][0] = *(const unsigned*)&As_l[r0];
                al[mf][1] = *(const unsigned*)&As_l[r0 + 8*SST];
                al[mf][2] = *(const unsigned*)&As_l[r0 + 8];
                al[mf][3] = *(const unsigned*)&As_l[r0 + 8*SST + 8];
            }
            #pragma unroll
            for (int nf = 0; nf < 4; nf++) {
                int c0 = (wn * 32 + nf * 8 + g) * SST + kk + t2;
                bh[nf][0] = *(const unsigned*)&Bs_h[c0];
                bh[nf][1] = *(const unsigned*)&Bs_h[c0 + 8];
                bl[nf][0] = *(const unsigned*)&Bs_l[c0];
                bl[nf][1] = *(const unsigned*)&Bs_l[c0 + 8];
            }
            #pragma unroll
            for (int mf = 0; mf < 4; mf++)
                #pragma unroll
                for (int nf = 0; nf < 4; nf++) {
                    MMA16816(acc[mf][nf], ah[mf], bh[nf]);
                    MMA16816(acc[mf][nf], ah[mf], bl[nf]);
                    MMA16816(acc[mf][nf], al[mf], bh[nf]);
                }
        }
        __syncthreads();
    }

    #pragma unroll
    for (int mf = 0; mf < 4; mf++) {
        int m0 = bm + wm * 64 + mf * 16 + g;
        #pragma unroll
        for (int nf = 0; nf < 4; nf++) {
            int n0 = bn + wn * 32 + nf * 8 + t2;
            #pragma unroll
            for (int c = 0; c < 4; c++) {
                int m = m0 + (c >> 1) * 8;
                int n = n0 + (c & 1);
                if (n >= N) continue;
                float v = acc[mf][nf][c];
                if (bias) v += bias[n];
                if (flags & 1) v = 0.5f * v * (1.0f + erff(v * 0.70710678118654752f));
                v *= alpha;
                long o = (long)m * N + n;
                if (flags & 2) C[o] += v; else C[o] = v;
            }
        }
    }
}

// ---------------- flash attention (tensor cores, bf16 split) -----------------
// grid (32 qtiles, H, B), 256 threads = 8 warps: wm=warp&3 (16 rows), wn=warp>>2
// (32 keys). Each warp runs online softmax over its key half; halves merged at
// the end via smem.
__global__ void __launch_bounds__(256, 1)
k_attn_fa()
{
    const int qt = (gridDim.x - 1) - blockIdx.x;   // heavy tiles first
    const int h  = blockIdx.y, b = blockIdx.z;
    const int tid  = threadIdx.x;
    const int lane = tid & 31, warp = tid >> 5;
    const int wm = warp & 3, wn = warp >> 2;
    const int g  = lane >> 2;
    const int t2 = (lane & 3) * 2;

    __shared__ __align__(16) char sm[4 * AKT * AST * 2];
    __nv_bfloat16* bufA_h = (__nv_bfloat16*)sm;                     // Q, then K
    __nv_bfloat16* bufA_l = (__nv_bfloat16*)(sm + AKT*AST*2);
    __nv_bfloat16* vt_h   = (__nv_bfloat16*)(sm + 2*AKT*AST*2);    // V^T
    __nv_bfloat16* vt_l   = (__nv_bfloat16*)(sm + 3*AKT*AST*2);
    float* Omrg = (float*)sm;                                       // reuse
    __shared__ float sm_m[AQT], sm_l[AQT];

    const long base = (long)(b * Tn) * (3 * Dm);
    const int  t0   = qt * AQT;

    // ---- stage Q (fp32 -> hi/lo), then preload Q frags -----------------------
    #pragma unroll
    for (int i = 0; i < 4; i++) {
        int idx = tid + i * 256;
        int r = idx >> 4, q = (idx & 15) * 4;
        float4 v = *(const float4*)&g_qkv[base + (long)(t0 + r) * (3*Dm) + h*HDm + q];
        __nv_bfloat16 h0,l0,h1,l1,h2,l2,h3,l3;
        bsplit(v.x,h0,l0); bsplit(v.y,h1,l1);
        bsplit(v.z,h2,l2); bsplit(v.w,h3,l3);
        int off = r * AST + q;
        *(__nv_bfloat162*)&bufA_h[off]   = __halves2bfloat162(h0,h1);
        *(__nv_bfloat162*)&bufA_h[off+2] = __halves2bfloat162(h2,h3);
        *(__nv_bfloat162*)&bufA_l[off]   = __halves2bfloat162(l0,l1);
        *(__nv_bfloat162*)&bufA_l[off+2] = __halves2bfloat162(l2,l3);
    }
    __syncthreads();

    unsigned qh[4][4], ql[4][4];
    #pragma unroll
    for (int kk = 0; kk < 4; kk++) {
        int r0 = (wm * 16 + g) * AST + kk * 16 + t2;
        qh[kk][0] = *(const unsigned*)&bufA_h[r0];
        qh[kk][1] = *(const unsigned*)&bufA_h[r0 + 8*AST];
        qh[kk][2] = *(const unsigned*)&bufA_h[r0 + 8];
        qh[kk][3] = *(const unsigned*)&bufA_h[r0 + 8*AST + 8];
        ql[kk][0] = *(const unsigned*)&bufA_l[r0];
        ql[kk][1] = *(const unsigned*)&bufA_l[r0 + 8*AST];
        ql[kk][2] = *(const unsigned*)&bufA_l[r0 + 8];
        ql[kk][3] = *(const unsigned*)&bufA_l[r0 + 8*AST + 8];
    }

    float oacc[8][4] = {};
    float mprev[2] = {-1e30f, -1e30f};
    float lsum [2] = {0.f, 0.f};

    for (int kt = 0; kt <= qt; kt++) {
        __syncthreads();   // Q frags read / previous tile consumed

        // ---- stage K (hi/lo) and V transposed (hi/lo) ----
        #pragma unroll
        for (int i = 0; i < 4; i++) {
            int idx = tid + i * 256;
            int r = idx >> 4, q = (idx & 15) * 4;
            long rowb = base + (long)(kt * AKT + r) * (3*Dm) + h*HDm + q;
            float4 kv = *(const float4*)&g_qkv[rowb + Dm];
            float4 vv = *(const float4*)&g_qkv[rowb + 2*Dm];
            __nv_bfloat16 h0,l0,h1,l1,h2,l2,h3,l3;
            bsplit(kv.x,h0,l0); bsplit(kv.y,h1,l1);
            bsplit(kv.z,h2,l2); bsplit(kv.w,h3,l3);
            int off = r * AST + q;
            *(__nv_bfloat162*)&bufA_h[off]   = __halves2bfloat162(h0,h1);
            *(__nv_bfloat162*)&bufA_h[off+2] = __halves2bfloat162(h2,h3);
            *(__nv_bfloat162*)&bufA_l[off]   = __halves2bfloat162(l0,l1);
            *(__nv_bfloat162*)&bufA_l[off+2] = __halves2bfloat162(l2,l3);
            float vf[4] = {vv.x, vv.y, vv.z, vv.w};
            #pragma unroll
            for (int e = 0; e < 4; e++) {
                __nv_bfloat16 vh, vl;
                bsplit(vf[e], vh, vl);
                vt_h[(q + e) * AST + r] = vh;
                vt_l[(q + e) * AST + r] = vl;
            }
        }
        __syncthreads();

        // ---- S = Q @ K^T (scaled), per-warp 16x32 slice ----
        float sacc[4][4] = {};
        #pragma unroll
        for (int kk = 0; kk < 4; kk++) {
            #pragma unroll
            for (int nf = 0; nf < 4; nf++) {
                unsigned bh[2], bl[2];
                int c0 = (wn * 32 + nf * 8 + g) * AST + kk * 16 + t2;
                bh[0] = *(const unsigned*)&bufA_h[c0];
                bh[1] = *(const unsigned*)&bufA_h[c0 + 8];
                bl[0] = *(const unsigned*)&bufA_l[c0];
                bl[1] = *(const unsigned*)&bufA_l[c0 + 8];
                MMA16816(sacc[nf], qh[kk], bh);
                MMA16816(sacc[nf], qh[kk], bl);
                MMA16816(sacc[nf], ql[kk], bh);
            }
        }

        // scale + causal mask on the diagonal tile
        const bool diag = (kt == qt);
        #pragma unroll
        for (int nf = 0; nf < 4; nf++)
            #pragma unroll
            for (int c = 0; c < 4; c++) {
                float v = sacc[nf][c] * 0.125f;
                if (diag) {
                    int key = wn * 32 + nf * 8 + t2 + (c & 1);
                    int row = wm * 16 + g + (c >> 1) * 8;
                    if (key > row) v = -1.7e38f;
                }
                sacc[nf][c] = v;
            }

        // ---- online softmax per thread-row ----
        float alpha[2];
        #pragma unroll
        for (int r = 0; r < 2; r++) {
            float rmax = -1.7e38f;
            #pragma unroll
            for (int nf = 0; nf < 4; nf++) {
                rmax = fmaxf(rmax, sacc[nf][2*r]);
                rmax = fmaxf(rmax, sacc[nf][2*r+1]);
            }
            rmax = fmaxf(rmax, __shfl_xor_sync(0xffffffffu, rmax, 1));
            rmax = fmaxf(rmax, __shfl_xor_sync(0xffffffffu, rmax, 2));
            float newm = fmaxf(mprev[r], rmax);
            alpha[r] = __expf(mprev[r] - newm);
            mprev[r] = newm;
            float ps = 0.f;
            #pragma unroll
            for (int nf = 0; nf < 4; nf++) {
                float p0 = __expf(sacc[nf][2*r]   - newm);
                float p1 = __expf(sacc[nf][2*r+1] - newm);
                sacc[nf][2*r] = p0; sacc[nf][2*r+1] = p1;
                ps += p0 + p1;
            }
            ps += __shfl_xor_sync(0xffffffffu, ps, 1);
            ps += __shfl_xor_sync(0xffffffffu, ps, 2);
            lsum[r] = lsum[r] * alpha[r] + ps;
        }
        #pragma unroll
        for (int nf = 0; nf < 8; nf++) {
            oacc[nf][0] *= alpha[0]; oacc[nf][1] *= alpha[0];
            oacc[nf][2] *= alpha[1]; oacc[nf][3] *= alpha[1];
        }

        // ---- O += P @ V ----
        #pragma unroll
        for (int k2 = 0; k2 < 2; k2++) {
            unsigned pah[4], pal[4];
            float* s0 = sacc[2*k2];
            float* s1 = sacc[2*k2+1];
            pah[0] = pack2(s0[0], s0[1]);
            pah[1] = pack2(s0[2], s0[3]);
            pah[2] = pack2(s1[0], s1[1]);
            pah[3] = pack2(s1[2], s1[3]);
            {
                __nv_bfloat162 t0h = *(__nv_bfloat162*)&pah[0];
                __nv_bfloat162 t1h = *(__nv_bfloat162*)&pah[1];
                __nv_bfloat162 t2h = *(__nv_bfloat162*)&pah[2];
                __nv_bfloat162 t3h = *(__nv_bfloat162*)&pah[3];
                pal[0] = pack2lo(s0[0], __bfloat162float(t0h.x), s0[1], __bfloat162float(t0h.y));
                pal[1] = pack2lo(s0[2], __bfloat162float(t1h.x), s0[3], __bfloat162float(t1h.y));
                pal[2] = pack2lo(s1[0], __bfloat162float(t2h.x), s1[1], __bfloat162float(t2h.y));
                pal[3] = pack2lo(s1[2], __bfloat162float(t3h.x), s1[3], __bfloat162float(t3h.y));
            }
            #pragma unroll
            for (int nf = 0; nf < 8; nf++) {
                unsigned vh[2], vl[2];
                int c0 = (nf * 8 + g) * AST + wn * 32 + k2 * 16 + t2;
                vh[0] = *(const unsigned*)&vt_h[c0];
                vh[1] = *(const unsigned*)&vt_h[c0 + 8];
                vl[0] = *(const unsigned*)&vt_l[c0];
                vl[1] = *(const unsigned*)&vt_l[c0 + 8];
                MMA16816(oacc[nf], pah, vh);
                MMA16816(oacc[nf], pah, vl);
                MMA16816(oacc[nf], pal, vh);
            }
        }
    }

    // ---- merge the two key-half warps, write out -----------------------------
    __syncthreads();
    if (wn == 1) {
        #pragma unroll
        for (int nf = 0; nf < 8; nf++) {
            int d0 = nf * 8 + t2;
            Omrg[(wm*16 + g    ) * 64 + d0    ] = oacc[nf][0];
            Omrg[(wm*16 + g    ) * 64 + d0 + 1] = oacc[nf][1];
            Omrg[(wm*16 + g + 8) * 64 + d0    ] = oacc[nf][2];
            Omrg[(wm*16 + g + 8) * 64 + d0 + 1] = oacc[nf][3];
        }
        if ((lane & 3) == 0) {
            sm_m[wm*16 + g    ] = mprev[0];
            sm_m[wm*16 + g + 8] = mprev[1];
            sm_l[wm*16 + g    ] = lsum[0];
            sm_l[wm*16 + g + 8] = lsum[1];
        }
    }
    __syncthreads();
    if (wn == 0) {
        #pragma unroll
        for (int r = 0; r < 2; r++) {
            int rl = wm*16 + g + 8*r;
            float m1 = sm_m[rl], l1 = sm_l[rl];
            float m  = fmaxf(mprev[r], m1);
            float a0 = __expf(mprev[r] - m);
            float a1 = __expf(m1 - m);
            float inv = 1.0f / (lsum[r] * a0 + l1 * a1);
            long orow = ((long)(b * Tn + t0 + rl)) * Dm + h * HDm;
            #pragma unroll
            for (int nf = 0; nf < 8; nf++) {
                int d0 = nf * 8 + t2;
                float v0 = (oacc[nf][2*r]   * a0 + Omrg[rl*64 + d0    ] * a1) * inv;
                float v1 = (oacc[nf][2*r+1] * a0 + Omrg[rl*64 + d0 + 1] * a1) * inv;
                g_attn[orow + d0    ] = v0;
                g_attn[orow + d0 + 1] = v1;
            }
        }
    }
}

// ---------------- residual add + LayerNorm -----------------------------------
__global__ void k_add_ln(const float* __restrict__ x,
                         const float* __restrict__ y,
                         const float* __restrict__ g,
                         const float* __restrict__ bta,
                         float* __restrict__ out)
{
    int row = blockIdx.x;
    int tid = threadIdx.x;
    __shared__ float buf[Dm];
    __shared__ float red[256];

    float psum = 0.f;
    for (int i = tid; i < Dm; i += 256) {
        float v = x[(long)row * Dm + i];
        if (y) v += y[(long)row * Dm + i];
        buf[i] = v;
        psum += v;
    }
    red[tid] = psum; __syncthreads();
    for (int s = 128; s > 0; s >>= 1) {
        if (tid < s) red[tid] += red[tid + s];
        __syncthreads();
    }
    float mu = red[0] * (1.0f / Dm); __syncthreads();

    float pvar = 0.f;
    for (int i = tid; i < Dm; i += 256) {
        float dv = buf[i] - mu;
        pvar += dv * dv;
    }
    red[tid] = pvar; __syncthreads();
    for (int s = 128; s > 0; s >>= 1) {
        if (tid < s) red[tid] += red[tid + s];
        __syncthreads();
    }
    float rstd = rsqrtf(red[0] * (1.0f / Dm) + EPSf); __syncthreads();

    for (int i = tid; i < Dm; i += 256)
        out[(long)row * Dm + i] = (buf[i] - mu) * rstd * g[i] + bta[i];
}

// ---------------- router ------------------------------------------------------
__global__ void k_router(const float* __restrict__ c_states,
                         const float* __restrict__ rw,
                         const float* __restrict__ rb)
{
    int tid = threadIdx.x;
    __shared__ float cm[CDm];
    __shared__ float lg[En];

    for (int d = tid; d < CDm; d += 256) {
        float s = 0.f;
        for (int r = 0; r < 64; r++) s += c_states[(long)r * CDm + d];
        cm[d] = s * (1.0f / 64.0f);
    }
    __syncthreads();
    if (tid < En) {
        float s = 0.f;
        const float* w = rw + (long)tid * CDm;
        for (int d = 0; d < CDm; d++) s += w[d] * cm[d];
        lg[tid] = s + rb[tid];
    }
    __syncthreads();
    if (tid == 0) {
        float mx = lg[0];
        for (int e = 1; e < En; e++) mx = fmaxf(mx, lg[e]);
        float p[En], sum = 0.f;
        for (int e = 0; e < En; e++) { p[e] = expf(lg[e] - mx); sum += p[e]; }
        for (int e = 0; e < En; e++) p[e] /= sum;
        int i0 = 0;
        for (int e = 1; e < En; e++) if (p[e] > p[i0]) i0 = e;
        int i1 = (i0 == 0) ? 1 : 0;
        for (int e = 0; e < En; e++) if (e != i0 && p[e] > p[i1]) i1 = e;
        float ws = p[i0] + p[i1];
        g_eidx[0] = i0; g_eidx[1] = i1;
        g_ew[0] = p[i0] / ws; g_ew[1] = p[i1] / ws;
    }
}

// ============================================================================
extern "C" void kernel_launch(void* const* d_in, const int* in_sizes, int n_in,
                              void* d_out, int out_size)
{
    const int*   tokens   = (const int*)  d_in[0];
    const float* c_states = (const float*)d_in[1];
    const float* embed_w  = (const float*)d_in[2];
    const float* pos_w    = (const float*)d_in[3];
    const float* in_w     = (const float*)d_in[4];
    const float* in_b     = (const float*)d_in[5];
    const float* out_w    = (const float*)d_in[6];
    const float* out_b    = (const float*)d_in[7];
    const float* ln_a_g   = (const float*)d_in[8];
    const float* ln_a_b   = (const float*)d_in[9];
    const float* router_w = (const float*)d_in[10];
    const float* router_b = (const float*)d_in[11];
    const float* e_w1     = (const float*)d_in[12];
    const float* e_b1     = (const float*)d_in[13];
    const float* e_w2     = (const float*)d_in[14];
    const float* e_b2     = (const float*)d_in[15];
    const float* ln_m_g   = (const float*)d_in[16];
    const float* ln_m_b   = (const float*)d_in[17];
    const float* ln_f_g   = (const float*)d_in[18];
    const float* ln_f_b   = (const float*)d_in[19];
    const float* head_w   = (const float*)d_in[20];
    float* out = (float*)d_out;

    float *p_x, *p_qkv, *p_attn, *p_tmp, *p_h, *p_moe, *p_xf;
    cudaGetSymbolAddress((void**)&p_x,    g_x);
    cudaGetSymbolAddress((void**)&p_qkv,  g_qkv);
    cudaGetSymbolAddress((void**)&p_attn, g_attn);
    cudaGetSymbolAddress((void**)&p_tmp,  g_tmp);
    cudaGetSymbolAddress((void**)&p_h,    g_h);
    cudaGetSymbolAddress((void**)&p_moe,  g_moe);
    cudaGetSymbolAddress((void**)&p_xf,   g_xf);

    dim3 blk(256);

    k_embed<<<BT, 256>>>(tokens, embed_w, pos_w);

    for (int l = 0; l < Lnum; l++) {
        {   // QKV projection
            dim3 grid((3 * Dm) / BN, BT / BM);
            k_gemm<<<grid, blk>>>(p_x, in_w + (long)l * 3 * Dm * Dm,
                                  in_b + (long)l * 3 * Dm, p_qkv,
                                  BT, 3 * Dm, Dm, 0, 0, 0, 0);
        }
        {   // flash attention
            dim3 grid(Tn / AQT, Hn, Bn);
            k_attn_fa<<<grid, 256>>>();
        }
        {   // output projection
            dim3 grid(Dm / BN, BT / BM);
            k_gemm<<<grid, blk>>>(p_attn, out_w + (long)l * Dm * Dm,
                                  out_b + (long)l * Dm, p_tmp,
                                  BT, Dm, Dm, 0, 0, 0, 0);
        }
        k_add_ln<<<BT, 256>>>(p_x, p_tmp, ln_a_g + l * Dm, ln_a_b + l * Dm, p_x);

        k_router<<<1, 256>>>(c_states, router_w + (long)l * En * CDm,
                             router_b + (long)l * En);

        for (int slot = 0; slot < 2; slot++) {
            {
                dim3 grid(Fm / BN, BT / BM);
                k_gemm<<<grid, blk>>>(p_x,
                                      e_w1 + (long)l * En * Fm * Dm,
                                      e_b1 + (long)l * En * Fm,
                                      p_h, BT, Fm, Dm,
                                      (long)Fm * Dm, (long)Fm,
                                      slot, 1 | 4);
            }
            {
                dim3 grid(Dm / BN, BT / BM);
                int flags = 4 | 8 | (slot == 1 ? 2 : 0);
                k_gemm<<<grid, blk>>>(p_h,
                                      e_w2 + (long)l * En * Dm * Fm,
                                      e_b2 + (long)l * En * Dm,
                                      p_moe, BT, Dm, Fm,
                                      (long)Dm * Fm, (long)Dm,
                                      slot, flags);
            }
        }
        k_add_ln<<<BT, 256>>>(p_x, p_moe, ln_m_g + l * Dm, ln_m_b + l * Dm, p_x);
    }

    k_add_ln<<<BT, 256>>>(p_x, nullptr, ln_f_g, ln_f_b, p_xf);

    {   // LM head
        dim3 grid((Vv + BN - 1) / BN, BT / BM);
        k_gemm<<<grid, blk>>>(p_xf, head_w, nullptr, out,
                              BT, Vv, Dm, 0, 0, 0, 0);
    }
}

// round 4
// speedup vs baseline: 8.5218x; 1.1003x over previous
#include <cuda_runtime.h>
#include <cuda_bf16.h>
#include <math.h>

#define Lnum 2
#define Dm   1024
#define Hn   16
#define HDm  64
#define Vv   50257
#define Tn   2048
#define Bn   2
#define BT   (Bn*Tn)        // 4096
#define CDm  512
#define En   8
#define Fm   4096
#define EPSf 1e-5f

// GEMM tiling
#define BM 128
#define BN 128
#define BK 32
#define SST 40                       // smem row stride (halves)
#define ARR_B (BM*SST*2)             // 10240 bytes per operand array
#define STG_B (4*ARR_B)              // 40960 bytes per stage
#define GEMM_SMEM (2*STG_B)          // 81920

// attention tiling
#define AQT 64
#define AKT 64
#define AST 72                       // attn smem row stride (halves)
#define AARR (AKT*AST*2)             // 9216
#define ASTG (4*AARR)                // 36864
#define ATT_SMEM (2*ASTG)            // 73728

// ---------------- scratch (static device globals) ----------------------------
__device__ float g_x  [BT*Dm];
__device__ float g_tmp[BT*Dm];
__device__ float g_moe[BT*Dm];
__device__ float g_xf [BT*Dm];

__device__ __nv_bfloat16 g_xh[BT*Dm],  g_xl[BT*Dm];
__device__ __nv_bfloat16 g_qkvh[(size_t)BT*3*Dm], g_qkvl[(size_t)BT*3*Dm];
__device__ __nv_bfloat16 g_ath[BT*Dm], g_atl[BT*Dm];
__device__ __nv_bfloat16 g_hh[(size_t)BT*Fm], g_hl[(size_t)BT*Fm];
__device__ __nv_bfloat16 g_xfh[BT*Dm], g_xfl[BT*Dm];

__device__ __nv_bfloat16 g_inwh[(size_t)Lnum*3*Dm*Dm], g_inwl[(size_t)Lnum*3*Dm*Dm];
__device__ __nv_bfloat16 g_outwh[(size_t)Lnum*Dm*Dm],  g_outwl[(size_t)Lnum*Dm*Dm];
__device__ __nv_bfloat16 g_headh[(size_t)Vv*Dm],       g_headl[(size_t)Vv*Dm];
__device__ __nv_bfloat16 g_w1h[(size_t)Lnum*2*Fm*Dm],  g_w1l[(size_t)Lnum*2*Fm*Dm];
__device__ __nv_bfloat16 g_w2h[(size_t)Lnum*2*Dm*Fm],  g_w2l[(size_t)Lnum*2*Dm*Fm];

__device__ int   g_eidx2[4];   // [layer*2+slot]
__device__ float g_ew2[4];

// ---------------- helpers -----------------------------------------------------
__device__ __forceinline__ void bsplit(float v, __nv_bfloat16& hi, __nv_bfloat16& lo)
{
    hi = __float2bfloat16(v);
    lo = __float2bfloat16(v - __bfloat162float(hi));
}
__device__ __forceinline__ unsigned pack2(float a, float b)
{
    __nv_bfloat162 t = __halves2bfloat162(__float2bfloat16(a), __float2bfloat16(b));
    return *(unsigned*)&t;
}
__device__ __forceinline__ unsigned pack2lo(float a, float ah, float b, float bh)
{
    __nv_bfloat162 t = __halves2bfloat162(__float2bfloat16(a - ah),
                                          __float2bfloat16(b - bh));
    return *(unsigned*)&t;
}

#define MMA16816(d, a, b) \
    asm volatile("mma.sync.aligned.m16n8k16.row.col.f32.bf16.bf16.f32 " \
                 "{%0,%1,%2,%3},{%4,%5,%6,%7},{%8,%9},{%0,%1,%2,%3};\n" \
                 : "+f"(d[0]), "+f"(d[1]), "+f"(d[2]), "+f"(d[3])       \
                 : "r"(a[0]), "r"(a[1]), "r"(a[2]), "r"(a[3]),          \
                   "r"(b[0]), "r"(b[1]))

#define LDSM4(r, addr) \
    asm volatile("ldmatrix.sync.aligned.m8n8.x4.shared.b16 {%0,%1,%2,%3}, [%4];" \
                 : "=r"(r[0]), "=r"(r[1]), "=r"(r[2]), "=r"(r[3]) : "r"(addr))
#define LDSM4T(r, addr) \
    asm volatile("ldmatrix.sync.aligned.m8n8.x4.trans.shared.b16 {%0,%1,%2,%3}, [%4];" \
                 : "=r"(r[0]), "=r"(r[1]), "=r"(r[2]), "=r"(r[3]) : "r"(addr))

__device__ __forceinline__ void cpa16(unsigned dst, const void* src, int bytes)
{
    asm volatile("cp.async.cg.shared.global [%0], [%1], 16, %2;"
                 :: "r"(dst), "l"(src), "r"(bytes));
}
#define CP_COMMIT() asm volatile("cp.async.commit_group;")
#define CP_WAIT1()  asm volatile("cp.async.wait_group 1;")
#define CP_WAIT0()  asm volatile("cp.async.wait_group 0;")

// ---------------- embed (fp32 + split) ----------------------------------------
__global__ void k_embed(const int* __restrict__ tokens,
                        const float* __restrict__ embed_w,
                        const float* __restrict__ pos_w)
{
    int row = blockIdx.x;
    int t   = row % Tn;
    int tok = tokens[row];
    const float* e = embed_w + (long)tok * Dm;
    const float* p = pos_w   + (long)t   * Dm;
    long o = (long)row * Dm;
    for (int d = threadIdx.x; d < Dm; d += blockDim.x) {
        float v = e[d] + p[d];
        g_x[o + d] = v;
        __nv_bfloat16 h, l; bsplit(v, h, l);
        g_xh[o + d] = h; g_xl[o + d] = l;
    }
}

// ---------------- weight split kernels ----------------------------------------
__global__ void k_split(const float* __restrict__ src,
                        __nv_bfloat16* __restrict__ dh,
                        __nv_bfloat16* __restrict__ dl, long n)
{
    long i = ((long)blockIdx.x * 256 + threadIdx.x) * 4;
    if (i >= n) return;
    float4 v = *(const float4*)&src[i];
    __nv_bfloat16 h0,l0,h1,l1,h2,l2,h3,l3;
    bsplit(v.x,h0,l0); bsplit(v.y,h1,l1); bsplit(v.z,h2,l2); bsplit(v.w,h3,l3);
    *(__nv_bfloat162*)&dh[i]   = __halves2bfloat162(h0,h1);
    *(__nv_bfloat162*)&dh[i+2] = __halves2bfloat162(h2,h3);
    *(__nv_bfloat162*)&dl[i]   = __halves2bfloat162(l0,l1);
    *(__nv_bfloat162*)&dl[i+2] = __halves2bfloat162(l2,l3);
}

__global__ void k_split_exp(const float* __restrict__ src,
                            __nv_bfloat16* __restrict__ dh,
                            __nv_bfloat16* __restrict__ dl,
                            long n, int sidx)
{
    long off = (long)g_eidx2[sidx] * n;
    long i = ((long)blockIdx.x * 256 + threadIdx.x) * 4;
    if (i >= n) return;
    float4 v = *(const float4*)&src[off + i];
    __nv_bfloat16 h0,l0,h1,l1,h2,l2,h3,l3;
    bsplit(v.x,h0,l0); bsplit(v.y,h1,l1); bsplit(v.z,h2,l2); bsplit(v.w,h3,l3);
    *(__nv_bfloat162*)&dh[i]   = __halves2bfloat162(h0,h1);
    *(__nv_bfloat162*)&dh[i+2] = __halves2bfloat162(h2,h3);
    *(__nv_bfloat162*)&dl[i]   = __halves2bfloat162(l0,l1);
    *(__nv_bfloat162*)&dl[i+2] = __halves2bfloat162(l2,l3);
}

// ---------------- GEMM v2: pre-split bf16 operands, cp.async pipelined --------
// C[M,N] = op(A[M,K] @ W[N,K]^T + bias)
// flags: 1=GELU, 2=ACCUM(into fp32 C), 4=SCALE by g_ew2[sidx], 8=expert bias offset
__global__ void __launch_bounds__(256, 2)
k_gemm2(const __nv_bfloat16* __restrict__ Ah, const __nv_bfloat16* __restrict__ Al,
        const __nv_bfloat16* __restrict__ Wh, const __nv_bfloat16* __restrict__ Wl,
        const float* __restrict__ bias,
        float* __restrict__ C,
        __nv_bfloat16* __restrict__ Ch, __nv_bfloat16* __restrict__ Cl,
        int M, int N, int K, int sidx, int flags)
{
    extern __shared__ char dsm[];
    const int bm = blockIdx.y * BM, bn = blockIdx.x * BN;
    const int tid = threadIdx.x, lane = tid & 31, warp = tid >> 5;
    const int wm = warp & 1, wn = warp >> 1;
    const int g = lane >> 2, t2 = (lane & 3) * 2;
    const unsigned sbase = (unsigned)__cvta_generic_to_shared(dsm);

    if (flags & 8) bias += (long)g_eidx2[sidx] * N;
    const float alpha = (flags & 4) ? g_ew2[sidx] : 1.0f;

#define LOAD_STAGE(s, k0)                                                     \
    {                                                                         \
        unsigned st = sbase + (s) * STG_B;                                    \
        _Pragma("unroll")                                                     \
        for (int j = 0; j < 8; j++) {                                         \
            int cid = tid + j * 256;                                          \
            int arr = cid >> 9;                                               \
            int w = cid & 511;                                                \
            int r = w >> 2;                                                   \
            int q = (w & 3) * 8;                                              \
            unsigned dst = st + arr * ARR_B + (r * SST + q) * 2;              \
            const __nv_bfloat16* src;                                         \
            int bytes = 16;                                                   \
            if (arr == 0)      src = Ah + (long)(bm + r) * K + (k0) + q;      \
            else if (arr == 1) src = Al + (long)(bm + r) * K + (k0) + q;      \
            else {                                                            \
                int nr = bn + r;                                              \
                const __nv_bfloat16* wb = (arr == 2) ? Wh : Wl;               \
                if (nr >= N) { nr = 0; bytes = 0; }                           \
                src = wb + (long)nr * K + (k0) + q;                           \
            }                                                                 \
            cpa16(dst, src, bytes);                                           \
        }                                                                     \
    }

    float acc[4][4][4] = {};

    const unsigned aRowOff = ((unsigned)(wm*64 + (lane&7) + ((lane>>3)&1)*8) * SST
                              + ((lane>>4)*8)) * 2;
    const unsigned bRowOff = ((unsigned)(wn*32 + (lane&7) + ((lane>>3)&1)*8) * SST
                              + ((lane>>4)*8)) * 2;

    const int nk = K / BK;
    LOAD_STAGE(0, 0);
    CP_COMMIT();

    for (int kt = 0; kt < nk; kt++) {
        if (kt + 1 < nk) {
            LOAD_STAGE((kt + 1) & 1, (kt + 1) * BK);
            CP_COMMIT();
            CP_WAIT1();
        } else {
            CP_WAIT0();
        }
        __syncthreads();

        unsigned stg = sbase + (kt & 1) * STG_B;
        #pragma unroll
        for (int kk = 0; kk < BK; kk += 16) {
            unsigned ah[4][4], al[4][4], bh[4][2], bl[4][2];
            #pragma unroll
            for (int mf = 0; mf < 4; mf++) {
                unsigned ad = stg + aRowOff + (mf*16*SST + kk) * 2;
                LDSM4(ah[mf], ad);
                LDSM4(al[mf], ad + ARR_B);
            }
            #pragma unroll
            for (int nfp = 0; nfp < 2; nfp++) {
                unsigned r4[4], s4[4];
                unsigned bd = stg + 2*ARR_B + bRowOff + (nfp*16*SST + kk) * 2;
                LDSM4(r4, bd);
                LDSM4(s4, bd + ARR_B);
                bh[2*nfp][0]   = r4[0]; bh[2*nfp][1]   = r4[2];
                bh[2*nfp+1][0] = r4[1]; bh[2*nfp+1][1] = r4[3];
                bl[2*nfp][0]   = s4[0]; bl[2*nfp][1]   = s4[2];
                bl[2*nfp+1][0] = s4[1]; bl[2*nfp+1][1] = s4[3];
            }
            #pragma unroll
            for (int mf = 0; mf < 4; mf++)
                #pragma unroll
                for (int nf = 0; nf < 4; nf++) {
                    MMA16816(acc[mf][nf], ah[mf], bh[nf]);
                    MMA16816(acc[mf][nf], ah[mf], bl[nf]);
                    MMA16816(acc[mf][nf], al[mf], bh[nf]);
                }
        }
        __syncthreads();
    }
#undef LOAD_STAGE

    // ---- epilogue ----
    #pragma unroll
    for (int mf = 0; mf < 4; mf++) {
        int m0 = bm + wm*64 + mf*16 + g;
        #pragma unroll
        for (int nf = 0; nf < 4; nf++) {
            int n0 = bn + wn*32 + nf*8 + t2;
            #pragma unroll
            for (int c = 0; c < 4; c++) {
                int m = m0 + (c >> 1) * 8;
                int n = n0 + (c & 1);
                if (n >= N) continue;
                float v = acc[mf][nf][c];
                if (bias) v += bias[n];
                if (flags & 1) v = 0.5f * v * (1.0f + erff(v * 0.70710678118654752f));
                v *= alpha;
                long o = (long)m * N + n;
                if (C) { if (flags & 2) C[o] += v; else C[o] = v; }
                if (Ch) {
                    __nv_bfloat16 h, l; bsplit(v, h, l);
                    Ch[o] = h; Cl[o] = l;
                }
            }
        }
    }
}

// ---------------- flash attention v2 (bf16 split inputs, cp.async) ------------
__global__ void __launch_bounds__(256)
k_attn_fa2()
{
    const int qt = (gridDim.x - 1) - blockIdx.x;
    const int h  = blockIdx.y, b = blockIdx.z;
    const int tid  = threadIdx.x;
    const int lane = tid & 31, warp = tid >> 5;
    const int wm = warp & 3, wn = warp >> 2;
    const int g  = lane >> 2;
    const int t2 = (lane & 3) * 2;

    extern __shared__ char dsm[];
    const unsigned sbase = (unsigned)__cvta_generic_to_shared(dsm);
    float* Omrg = (float*)dsm;
    __shared__ float sm_m[AQT], sm_l[AQT];

    const long rb3 = 3 * Dm;
    const int  t0  = qt * AQT;
    const long rowbase = (long)(b * Tn);

    // ---- stage Q (plain copies into stage0 K area), load Q frags -------------
    #pragma unroll
    for (int j = 0; j < 4; j++) {
        int cid = tid + j * 256;
        int arr = cid >> 9;
        int w = cid & 511;
        int r = w >> 3, q = (w & 7) * 8;
        const __nv_bfloat16* src = (arr ? g_qkvl : g_qkvh)
                                   + (rowbase + t0 + r) * rb3 + h * HDm + q;
        *(uint4*)(dsm + arr * AARR + (r * AST + q) * 2) = *(const uint4*)src;
    }
    __syncthreads();

    unsigned qh[4][4], ql[4][4];
    const unsigned qRowOff = ((unsigned)(wm*16 + (lane&7) + ((lane>>3)&1)*8) * AST
                              + ((lane>>4)*8)) * 2;
    #pragma unroll
    for (int kk = 0; kk < 4; kk++) {
        unsigned qa = sbase + qRowOff + kk * 16 * 2;
        LDSM4(qh[kk], qa);
        LDSM4(ql[kk], qa + AARR);
    }
    __syncthreads();

#define LOAD_KV(s, kt)                                                        \
    {                                                                         \
        unsigned st = sbase + (s) * ASTG;                                     \
        _Pragma("unroll")                                                     \
        for (int j = 0; j < 8; j++) {                                         \
            int cid = tid + j * 256;                                          \
            int arr = cid >> 9;                                               \
            int w = cid & 511;                                                \
            int r = w >> 3, q = (w & 7) * 8;                                  \
            const __nv_bfloat16* base = (arr & 1) ? g_qkvl : g_qkvh;          \
            long srow = (rowbase + (kt) * AKT + r) * rb3 + h * HDm + q        \
                        + ((arr >> 1) ? 2 * Dm : Dm);                         \
            cpa16(st + arr * AARR + (r * AST + q) * 2, base + srow, 16);      \
        }                                                                     \
    }

    float oacc[8][4] = {};
    float mprev[2] = {-1e30f, -1e30f};
    float lsum [2] = {0.f, 0.f};

    const unsigned kRowOff = ((unsigned)(wn*32 + (lane&7) + ((lane>>3)&1)*8) * AST
                              + ((lane>>4)*8)) * 2;
    const unsigned vRowBase = ((unsigned)(wn*32 + (lane&7) + ((lane>>3)&1)*8) * AST
                               + ((lane>>4)*8)) * 2;

    LOAD_KV(0, 0);
    CP_COMMIT();

    for (int kt = 0; kt <= qt; kt++) {
        if (kt < qt) {
            LOAD_KV((kt + 1) & 1, kt + 1);
            CP_COMMIT();
            CP_WAIT1();
        } else {
            CP_WAIT0();
        }
        __syncthreads();

        unsigned stg = sbase + (kt & 1) * ASTG;

        // ---- S = Q @ K^T ----
        float sacc[4][4] = {};
        #pragma unroll
        for (int kk = 0; kk < 4; kk++) {
            #pragma unroll
            for (int nfp = 0; nfp < 2; nfp++) {
                unsigned r4[4], s4[4];
                unsigned kd = stg + kRowOff + (nfp*16*AST + kk*16) * 2;
                LDSM4(r4, kd);
                LDSM4(s4, kd + AARR);
                unsigned bh0[2] = {r4[0], r4[2]}, bh1[2] = {r4[1], r4[3]};
                unsigned bl0[2] = {s4[0], s4[2]}, bl1[2] = {s4[1], s4[3]};
                MMA16816(sacc[2*nfp],   qh[kk], bh0);
                MMA16816(sacc[2*nfp],   qh[kk], bl0);
                MMA16816(sacc[2*nfp],   ql[kk], bh0);
                MMA16816(sacc[2*nfp+1], qh[kk], bh1);
                MMA16816(sacc[2*nfp+1], qh[kk], bl1);
                MMA16816(sacc[2*nfp+1], ql[kk], bh1);
            }
        }

        const bool diag = (kt == qt);
        #pragma unroll
        for (int nf = 0; nf < 4; nf++)
            #pragma unroll
            for (int c = 0; c < 4; c++) {
                float v = sacc[nf][c] * 0.125f;
                if (diag) {
                    int key = wn * 32 + nf * 8 + t2 + (c & 1);
                    int row = wm * 16 + g + (c >> 1) * 8;
                    if (key > row) v = -1.7e38f;
                }
                sacc[nf][c] = v;
            }

        // ---- online softmax ----
        float alpha[2];
        #pragma unroll
        for (int r = 0; r < 2; r++) {
            float rmax = -1.7e38f;
            #pragma unroll
            for (int nf = 0; nf < 4; nf++) {
                rmax = fmaxf(rmax, sacc[nf][2*r]);
                rmax = fmaxf(rmax, sacc[nf][2*r+1]);
            }
            rmax = fmaxf(rmax, __shfl_xor_sync(0xffffffffu, rmax, 1));
            rmax = fmaxf(rmax, __shfl_xor_sync(0xffffffffu, rmax, 2));
            float newm = fmaxf(mprev[r], rmax);
            alpha[r] = __expf(mprev[r] - newm);
            mprev[r] = newm;
            float ps = 0.f;
            #pragma unroll
            for (int nf = 0; nf < 4; nf++) {
                float p0 = __expf(sacc[nf][2*r]   - newm);
                float p1 = __expf(sacc[nf][2*r+1] - newm);
                sacc[nf][2*r] = p0; sacc[nf][2*r+1] = p1;
                ps += p0 + p1;
            }
            ps += __shfl_xor_sync(0xffffffffu, ps, 1);
            ps += __shfl_xor_sync(0xffffffffu, ps, 2);
            lsum[r] = lsum[r] * alpha[r] + ps;
        }
        #pragma unroll
        for (int nf = 0; nf < 8; nf++) {
            oacc[nf][0] *= alpha[0]; oacc[nf][1] *= alpha[0];
            oacc[nf][2] *= alpha[1]; oacc[nf][3] *= alpha[1];
        }

        // ---- O += P @ V  (V row-major, ldmatrix.trans) ----
        #pragma unroll
        for (int k2 = 0; k2 < 2; k2++) {
            unsigned pah[4], pal[4];
            float* s0 = sacc[2*k2];
            float* s1 = sacc[2*k2+1];
            pah[0] = pack2(s0[0], s0[1]);
            pah[1] = pack2(s0[2], s0[3]);
            pah[2] = pack2(s1[0], s1[1]);
            pah[3] = pack2(s1[2], s1[3]);
            {
                __nv_bfloat162 t0h = *(__nv_bfloat162*)&pah[0];
                __nv_bfloat162 t1h = *(__nv_bfloat162*)&pah[1];
                __nv_bfloat162 t2h = *(__nv_bfloat162*)&pah[2];
                __nv_bfloat162 t3h = *(__nv_bfloat162*)&pah[3];
                pal[0] = pack2lo(s0[0], __bfloat162float(t0h.x), s0[1], __bfloat162float(t0h.y));
                pal[1] = pack2lo(s0[2], __bfloat162float(t1h.x), s0[3], __bfloat162float(t1h.y));
                pal[2] = pack2lo(s1[0], __bfloat162float(t2h.x), s1[1], __bfloat162float(t2h.y));
                pal[3] = pack2lo(s1[2], __bfloat162float(t3h.x), s1[3], __bfloat162float(t3h.y));
            }
            unsigned vRow = ((unsigned)(wn*32 + k2*16 + (lane&7) + ((lane>>3)&1)*8) * AST
                             + ((lane>>4)*8)) * 2;
            #pragma unroll
            for (int nfp = 0; nfp < 4; nfp++) {
                unsigned r4[4], s4[4];
                unsigned vd = stg + 2*AARR + vRow + nfp * 16 * 2;
                LDSM4T(r4, vd);
                LDSM4T(s4, vd + AARR);
                unsigned vh0[2] = {r4[0], r4[1]}, vh1[2] = {r4[2], r4[3]};
                unsigned vl0[2] = {s4[0], s4[1]}, vl1[2] = {s4[2], s4[3]};
                MMA16816(oacc[2*nfp],   pah, vh0);
                MMA16816(oacc[2*nfp],   pah, vl0);
                MMA16816(oacc[2*nfp],   pal, vh0);
                MMA16816(oacc[2*nfp+1], pah, vh1);
                MMA16816(oacc[2*nfp+1], pah, vl1);
                MMA16816(oacc[2*nfp+1], pal, vh1);
            }
        }
        __syncthreads();
    }
#undef LOAD_KV

    // ---- merge key-half warps, write bf16 hi/lo output ------------------------
    if (wn == 1) {
        #pragma unroll
        for (int nf = 0; nf < 8; nf++) {
            int d0 = nf * 8 + t2;
            Omrg[(wm*16 + g    ) * 64 + d0    ] = oacc[nf][0];
            Omrg[(wm*16 + g    ) * 64 + d0 + 1] = oacc[nf][1];
            Omrg[(wm*16 + g + 8) * 64 + d0    ] = oacc[nf][2];
            Omrg[(wm*16 + g + 8) * 64 + d0 + 1] = oacc[nf][3];
        }
        if ((lane & 3) == 0) {
            sm_m[wm*16 + g    ] = mprev[0];
            sm_m[wm*16 + g + 8] = mprev[1];
            sm_l[wm*16 + g    ] = lsum[0];
            sm_l[wm*16 + g + 8] = lsum[1];
        }
    }
    __syncthreads();
    if (wn == 0) {
        #pragma unroll
        for (int r = 0; r < 2; r++) {
            int rl = wm*16 + g + 8*r;
            float m1 = sm_m[rl], l1 = sm_l[rl];
            float m  = fmaxf(mprev[r], m1);
            float a0 = __expf(mprev[r] - m);
            float a1 = __expf(m1 - m);
            float inv = 1.0f / (lsum[r] * a0 + l1 * a1);
            long orow = ((long)(b * Tn + t0 + rl)) * Dm + h * HDm;
            #pragma unroll
            for (int nf = 0; nf < 8; nf++) {
                int d0 = nf * 8 + t2;
                float v0 = (oacc[nf][2*r]   * a0 + Omrg[rl*64 + d0    ] * a1) * inv;
                float v1 = (oacc[nf][2*r+1] * a0 + Omrg[rl*64 + d0 + 1] * a1) * inv;
                __nv_bfloat16 h0, l0, h1, l1b;
                bsplit(v0, h0, l0); bsplit(v1, h1, l1b);
                g_ath[orow + d0] = h0; g_ath[orow + d0 + 1] = h1;
                g_atl[orow + d0] = l0; g_atl[orow + d0 + 1] = l1b;
            }
        }
    }
}

// ---------------- residual add + LayerNorm (+ split out) ----------------------
__global__ void k_add_ln(const float* __restrict__ x,
                         const float* __restrict__ y,
                         const float* __restrict__ g,
                         const float* __restrict__ bta,
                         float* __restrict__ out,
                         __nv_bfloat16* __restrict__ oh,
                         __nv_bfloat16* __restrict__ ol)
{
    int row = blockIdx.x;
    int tid = threadIdx.x;
    __shared__ float buf[Dm];
    __shared__ float red[256];

    float psum = 0.f;
    for (int i = tid; i < Dm; i += 256) {
        float v = x[(long)row * Dm + i];
        if (y) v += y[(long)row * Dm + i];
        buf[i] = v;
        psum += v;
    }
    red[tid] = psum; __syncthreads();
    for (int s = 128; s > 0; s >>= 1) {
        if (tid < s) red[tid] += red[tid + s];
        __syncthreads();
    }
    float mu = red[0] * (1.0f / Dm); __syncthreads();

    float pvar = 0.f;
    for (int i = tid; i < Dm; i += 256) {
        float dv = buf[i] - mu;
        pvar += dv * dv;
    }
    red[tid] = pvar; __syncthreads();
    for (int s = 128; s > 0; s >>= 1) {
        if (tid < s) red[tid] += red[tid + s];
        __syncthreads();
    }
    float rstd = rsqrtf(red[0] * (1.0f / Dm) + EPSf); __syncthreads();

    for (int i = tid; i < Dm; i += 256) {
        float v = (buf[i] - mu) * rstd * g[i] + bta[i];
        long o = (long)row * Dm + i;
        out[o] = v;
        __nv_bfloat16 h, l; bsplit(v, h, l);
        oh[o] = h; ol[o] = l;
    }
}

// ---------------- router -------------------------------------------------------
__global__ void k_router(const float* __restrict__ c_states,
                         const float* __restrict__ rw,
                         const float* __restrict__ rb, int layer)
{
    int tid = threadIdx.x;
    __shared__ float cm[CDm];
    __shared__ float lg[En];

    for (int d = tid; d < CDm; d += 256) {
        float s = 0.f;
        for (int r = 0; r < 64; r++) s += c_states[(long)r * CDm + d];
        cm[d] = s * (1.0f / 64.0f);
    }
    __syncthreads();
    if (tid < En) {
        float s = 0.f;
        const float* w = rw + (long)tid * CDm;
        for (int d = 0; d < CDm; d++) s += w[d] * cm[d];
        lg[tid] = s + rb[tid];
    }
    __syncthreads();
    if (tid == 0) {
        float mx = lg[0];
        for (int e = 1; e < En; e++) mx = fmaxf(mx, lg[e]);
        float p[En], sum = 0.f;
        for (int e = 0; e < En; e++) { p[e] = expf(lg[e] - mx); sum += p[e]; }
        for (int e = 0; e < En; e++) p[e] /= sum;
        int i0 = 0;
        for (int e = 1; e < En; e++) if (p[e] > p[i0]) i0 = e;
        int i1 = (i0 == 0) ? 1 : 0;
        for (int e = 0; e < En; e++) if (e != i0 && p[e] > p[i1]) i1 = e;
        float ws = p[i0] + p[i1];
        g_eidx2[layer*2 + 0] = i0; g_eidx2[layer*2 + 1] = i1;
        g_ew2[layer*2 + 0] = p[i0] / ws; g_ew2[layer*2 + 1] = p[i1] / ws;
    }
}

// ============================================================================
extern "C" void kernel_launch(void* const* d_in, const int* in_sizes, int n_in,
                              void* d_out, int out_size)
{
    const int*   tokens   = (const int*)  d_in[0];
    const float* c_states = (const float*)d_in[1];
    const float* embed_w  = (const float*)d_in[2];
    const float* pos_w    = (const float*)d_in[3];
    const float* in_w     = (const float*)d_in[4];
    const float* in_b     = (const float*)d_in[5];
    const float* out_w    = (const float*)d_in[6];
    const float* out_b    = (const float*)d_in[7];
    const float* ln_a_g   = (const float*)d_in[8];
    const float* ln_a_b   = (const float*)d_in[9];
    const float* router_w = (const float*)d_in[10];
    const float* router_b = (const float*)d_in[11];
    const float* e_w1     = (const float*)d_in[12];
    const float* e_b1     = (const float*)d_in[13];
    const float* e_w2     = (const float*)d_in[14];
    const float* e_b2     = (const float*)d_in[15];
    const float* ln_m_g   = (const float*)d_in[16];
    const float* ln_m_b   = (const float*)d_in[17];
    const float* ln_f_g   = (const float*)d_in[18];
    const float* ln_f_b   = (const float*)d_in[19];
    const float* head_w   = (const float*)d_in[20];
    float* out = (float*)d_out;

    cudaFuncSetAttribute(k_gemm2,   cudaFuncAttributeMaxDynamicSharedMemorySize, GEMM_SMEM);
    cudaFuncSetAttribute(k_attn_fa2, cudaFuncAttributeMaxDynamicSharedMemorySize, ATT_SMEM);

    float *p_x, *p_tmp, *p_moe, *p_xf;
    __nv_bfloat16 *p_xh,*p_xl,*p_qkvh,*p_qkvl,*p_ath,*p_atl,*p_hh,*p_hl,*p_xfh,*p_xfl;
    __nv_bfloat16 *p_inwh,*p_inwl,*p_outwh,*p_outwl,*p_headh,*p_headl;
    __nv_bfloat16 *p_w1h,*p_w1l,*p_w2h,*p_w2l;
    cudaGetSymbolAddress((void**)&p_x,    g_x);
    cudaGetSymbolAddress((void**)&p_tmp,  g_tmp);
    cudaGetSymbolAddress((void**)&p_moe,  g_moe);
    cudaGetSymbolAddress((void**)&p_xf,   g_xf);
    cudaGetSymbolAddress((void**)&p_xh,   g_xh);
    cudaGetSymbolAddress((void**)&p_xl,   g_xl);
    cudaGetSymbolAddress((void**)&p_qkvh, g_qkvh);
    cudaGetSymbolAddress((void**)&p_qkvl, g_qkvl);
    cudaGetSymbolAddress((void**)&p_ath,  g_ath);
    cudaGetSymbolAddress((void**)&p_atl,  g_atl);
    cudaGetSymbolAddress((void**)&p_hh,   g_hh);
    cudaGetSymbolAddress((void**)&p_hl,   g_hl);
    cudaGetSymbolAddress((void**)&p_xfh,  g_xfh);
    cudaGetSymbolAddress((void**)&p_xfl,  g_xfl);
    cudaGetSymbolAddress((void**)&p_inwh, g_inwh);
    cudaGetSymbolAddress((void**)&p_inwl, g_inwl);
    cudaGetSymbolAddress((void**)&p_outwh,g_outwh);
    cudaGetSymbolAddress((void**)&p_outwl,g_outwl);
    cudaGetSymbolAddress((void**)&p_headh,g_headh);
    cudaGetSymbolAddress((void**)&p_headl,g_headl);
    cudaGetSymbolAddress((void**)&p_w1h,  g_w1h);
    cudaGetSymbolAddress((void**)&p_w1l,  g_w1l);
    cudaGetSymbolAddress((void**)&p_w2h,  g_w2h);
    cudaGetSymbolAddress((void**)&p_w2l,  g_w2l);

    // ---- routers (input-independent of x) ----
    for (int l = 0; l < Lnum; l++)
        k_router<<<1, 256>>>(c_states, router_w + (long)l * En * CDm,
                             router_b + (long)l * En, l);

    // ---- weight pre-splits ----
    {
        long n;
        n = (long)Lnum * 3 * Dm * Dm;
        k_split<<<(unsigned)((n/4 + 255) / 256), 256>>>(in_w, p_inwh, p_inwl, n);
        n = (long)Lnum * Dm * Dm;
        k_split<<<(unsigned)((n/4 + 255) / 256), 256>>>(out_w, p_outwh, p_outwl, n);
        n = (long)Vv * Dm;
        k_split<<<(unsigned)((n/4 + 255) / 256), 256>>>(head_w, p_headh, p_headl, n);
        long ne = (long)Fm * Dm;   // per-expert elements (same for w1 and w2)
        unsigned ge = (unsigned)((ne/4 + 255) / 256);
        for (int l = 0; l < Lnum; l++)
            for (int s = 0; s < 2; s++) {
                int sidx = l*2 + s;
                k_split_exp<<<ge, 256>>>(e_w1 + (long)l * En * Fm * Dm,
                                         p_w1h + (long)sidx * ne,
                                         p_w1l + (long)sidx * ne, ne, sidx);
                k_split_exp<<<ge, 256>>>(e_w2 + (long)l * En * Dm * Fm,
                                         p_w2h + (long)sidx * ne,
                                         p_w2l + (long)sidx * ne, ne, sidx);
            }
    }

    k_embed<<<BT, 256>>>(tokens, embed_w, pos_w);

    dim3 blk(256);
    for (int l = 0; l < Lnum; l++) {
        {   // QKV projection -> split qkv
            dim3 grid((3 * Dm) / BN, BT / BM);
            k_gemm2<<<grid, blk, GEMM_SMEM>>>(
                p_xh, p_xl,
                p_inwh + (long)l * 3 * Dm * Dm, p_inwl + (long)l * 3 * Dm * Dm,
                in_b + (long)l * 3 * Dm,
                nullptr, p_qkvh, p_qkvl,
                BT, 3 * Dm, Dm, 0, 0);
        }
        {   // flash attention -> split attn
            dim3 grid(Tn / AQT, Hn, Bn);
            k_attn_fa2<<<grid, 256, ATT_SMEM>>>();
        }
        {   // output projection -> fp32 tmp
            dim3 grid(Dm / BN, BT / BM);
            k_gemm2<<<grid, blk, GEMM_SMEM>>>(
                p_ath, p_atl,
                p_outwh + (long)l * Dm * Dm, p_outwl + (long)l * Dm * Dm,
                out_b + (long)l * Dm,
                p_tmp, nullptr, nullptr,
                BT, Dm, Dm, 0, 0);
        }
        k_add_ln<<<BT, 256>>>(p_x, p_tmp, ln_a_g + l * Dm, ln_a_b + l * Dm,
                              p_x, p_xh, p_xl);

        for (int s = 0; s < 2; s++) {
            int sidx = l*2 + s;
            long ne = (long)Fm * Dm;
            {   // expert W1: GELU -> split h
                dim3 grid(Fm / BN, BT / BM);
                k_gemm2<<<grid, blk, GEMM_SMEM>>>(
                    p_xh, p_xl,
                    p_w1h + (long)sidx * ne, p_w1l + (long)sidx * ne,
                    e_b1 + (long)l * En * Fm,
                    nullptr, p_hh, p_hl,
                    BT, Fm, Dm, sidx, 1 | 8);
            }
            {   // expert W2: scale (+accum) -> fp32 moe
                dim3 grid(Dm / BN, BT / BM);
                int flags = 4 | 8 | (s == 1 ? 2 : 0);
                k_gemm2<<<grid, blk, GEMM_SMEM>>>(
                    p_hh, p_hl,
                    p_w2h + (long)sidx * ne, p_w2l + (long)sidx * ne,
                    e_b2 + (long)l * En * Dm,
                    p_moe, nullptr, nullptr,
                    BT, Dm, Fm, sidx, flags);
            }
        }
        k_add_ln<<<BT, 256>>>(p_x, p_moe, ln_m_g + l * Dm, ln_m_b + l * Dm,
                              p_x, p_xh, p_xl);
    }

    k_add_ln<<<BT, 256>>>(p_x, nullptr, ln_f_g, ln_f_b, p_xf, p_xfh, p_xfl);

    {   // LM head
        dim3 grid((Vv + BN - 1) / BN, BT / BM);
        k_gemm2<<<grid, blk, GEMM_SMEM>>>(
            p_xfh, p_xfl, p_headh, p_headl, nullptr,
            out, nullptr, nullptr,
            BT, Vv, Dm, 0, 0);
    }
}

// round 5
// speedup vs baseline: 19.0871x; 2.2398x over previous
#include <cuda_runtime.h>
#include <cuda_fp16.h>
#include <math.h>

#define Lnum 2
#define Dm   1024
#define Hn   16
#define HDm  64
#define Vv   50257
#define Tn   2048
#define Bn   2
#define BT   (Bn*Tn)        // 4096
#define CDm  512
#define En   8
#define Fm   4096
#define EPSf 1e-5f

// GEMM tiling
#define BM 128
#define BN 128
#define BK 32
#define SST 40                       // smem row stride (halves)
#define ARR_B (BM*SST*2)             // 10240 bytes per operand array
#define STG_B (2*ARR_B)              // 20480 bytes per stage (A + W)
#define GEMM_SMEM (2*STG_B)          // 40960

// attention tiling
#define AQT 64
#define AKT 64
#define AST 72                       // attn smem row stride (halves)
#define AARR (AKT*AST*2)             // 9216
#define ASTG (2*AARR)                // 18432 (K + V)
#define ATT_SMEM (2*ASTG)            // 36864

// ---------------- scratch (static device globals) ----------------------------
__device__ float g_x  [BT*Dm];
__device__ float g_tmp[BT*Dm];
__device__ float g_moe[BT*Dm];
__device__ float g_xf [BT*Dm];

__device__ __half g_xh [BT*Dm];
__device__ __half g_qkvh[(size_t)BT*3*Dm];
__device__ __half g_ath[BT*Dm];
__device__ __half g_hh [(size_t)BT*Fm];
__device__ __half g_xfh[BT*Dm];

__device__ __half g_inwh [(size_t)Lnum*3*Dm*Dm];
__device__ __half g_outwh[(size_t)Lnum*Dm*Dm];
__device__ __half g_headh[(size_t)Vv*Dm];
__device__ __half g_w1h  [(size_t)Lnum*2*Fm*Dm];
__device__ __half g_w2h  [(size_t)Lnum*2*Dm*Fm];

__device__ int   g_eidx2[4];   // [layer*2+slot]
__device__ float g_ew2[4];

// ---------------- helpers -----------------------------------------------------
__device__ __forceinline__ unsigned pack2h(float a, float b)
{
    __half2 t = __halves2half2(__float2half(a), __float2half(b));
    return *(unsigned*)&t;
}

#define MMAF16(d, a, b) \
    asm volatile("mma.sync.aligned.m16n8k16.row.col.f32.f16.f16.f32 " \
                 "{%0,%1,%2,%3},{%4,%5,%6,%7},{%8,%9},{%0,%1,%2,%3};\n" \
                 : "+f"(d[0]), "+f"(d[1]), "+f"(d[2]), "+f"(d[3])       \
                 : "r"(a[0]), "r"(a[1]), "r"(a[2]), "r"(a[3]),          \
                   "r"(b[0]), "r"(b[1]))

#define LDSM4(r, addr) \
    asm volatile("ldmatrix.sync.aligned.m8n8.x4.shared.b16 {%0,%1,%2,%3}, [%4];" \
                 : "=r"(r[0]), "=r"(r[1]), "=r"(r[2]), "=r"(r[3]) : "r"(addr))
#define LDSM4T(r, addr) \
    asm volatile("ldmatrix.sync.aligned.m8n8.x4.trans.shared.b16 {%0,%1,%2,%3}, [%4];" \
                 : "=r"(r[0]), "=r"(r[1]), "=r"(r[2]), "=r"(r[3]) : "r"(addr))

__device__ __forceinline__ void cpa16(unsigned dst, const void* src, int bytes)
{
    asm volatile("cp.async.cg.shared.global [%0], [%1], 16, %2;"
                 :: "r"(dst), "l"(src), "r"(bytes));
}
#define CP_COMMIT() asm volatile("cp.async.commit_group;")
#define CP_WAIT1()  asm volatile("cp.async.wait_group 1;")
#define CP_WAIT0()  asm volatile("cp.async.wait_group 0;")

// ---------------- embed (fp32 + fp16) ------------------------------------------
__global__ void k_embed(const int* __restrict__ tokens,
                        const float* __restrict__ embed_w,
                        const float* __restrict__ pos_w)
{
    int row = blockIdx.x;
    int t   = row % Tn;
    int tok = tokens[row];
    const float* e = embed_w + (long)tok * Dm;
    const float* p = pos_w   + (long)t   * Dm;
    long o = (long)row * Dm;
    for (int d = threadIdx.x; d < Dm; d += blockDim.x) {
        float v = e[d] + p[d];
        g_x[o + d]  = v;
        g_xh[o + d] = __float2half(v);
    }
}

// ---------------- weight conversion kernels ------------------------------------
__global__ void k_half(const float* __restrict__ src,
                       __half* __restrict__ dst, long n)
{
    long i = ((long)blockIdx.x * 256 + threadIdx.x) * 4;
    if (i >= n) return;
    float4 v = *(const float4*)&src[i];
    __half2 a = __halves2half2(__float2half(v.x), __float2half(v.y));
    __half2 b = __halves2half2(__float2half(v.z), __float2half(v.w));
    *(__half2*)&dst[i]   = a;
    *(__half2*)&dst[i+2] = b;
}

__global__ void k_half_exp(const float* __restrict__ src,
                           __half* __restrict__ dst, long n, int sidx)
{
    long off = (long)g_eidx2[sidx] * n;
    long i = ((long)blockIdx.x * 256 + threadIdx.x) * 4;
    if (i >= n) return;
    float4 v = *(const float4*)&src[off + i];
    __half2 a = __halves2half2(__float2half(v.x), __float2half(v.y));
    __half2 b = __halves2half2(__float2half(v.z), __float2half(v.w));
    *(__half2*)&dst[i]   = a;
    *(__half2*)&dst[i+2] = b;
}

// ---------------- GEMM v3: fp16 single-pass, cp.async pipelined ----------------
// C[M,N] = op(A[M,K] @ W[N,K]^T + bias)
// flags: 1=GELU, 2=ACCUM(into fp32 C), 4=SCALE by g_ew2[sidx], 8=expert bias offset
__global__ void __launch_bounds__(256, 2)
k_gemm3(const __half* __restrict__ A,
        const __half* __restrict__ W,
        const float* __restrict__ bias,
        float* __restrict__ C,
        __half* __restrict__ Ch,
        int M, int N, int K, int sidx, int flags)
{
    extern __shared__ char dsm[];
    const int bm = blockIdx.y * BM, bn = blockIdx.x * BN;
    const int tid = threadIdx.x, lane = tid & 31, warp = tid >> 5;
    const int wm = warp & 1, wn = warp >> 1;
    const int g = lane >> 2, t2 = (lane & 3) * 2;
    const unsigned sbase = (unsigned)__cvta_generic_to_shared(dsm);

    if (flags & 8) bias += (long)g_eidx2[sidx] * N;
    const float alpha = (flags & 4) ? g_ew2[sidx] : 1.0f;

#define LOAD_STAGE(s, k0)                                                     \
    {                                                                         \
        unsigned st = sbase + (s) * STG_B;                                    \
        _Pragma("unroll")                                                     \
        for (int j = 0; j < 4; j++) {                                         \
            int cid = tid + j * 256;                                          \
            int arr = cid >> 9;                                               \
            int w = cid & 511;                                                \
            int r = w >> 2;                                                   \
            int q = (w & 3) * 8;                                              \
            unsigned dst = st + arr * ARR_B + (r * SST + q) * 2;              \
            const __half* src;                                                \
            int bytes = 16;                                                   \
            if (arr == 0) src = A + (long)(bm + r) * K + (k0) + q;            \
            else {                                                            \
                int nr = bn + r;                                              \
                if (nr >= N) { nr = 0; bytes = 0; }                           \
                src = W + (long)nr * K + (k0) + q;                            \
            }                                                                 \
            cpa16(dst, src, bytes);                                           \
        }                                                                     \
    }

    float acc[4][4][4] = {};

    const unsigned aRowOff = ((unsigned)(wm*64 + (lane&7) + ((lane>>3)&1)*8) * SST
                              + ((lane>>4)*8)) * 2;
    const unsigned bRowOff = ((unsigned)(wn*32 + (lane&7) + ((lane>>3)&1)*8) * SST
                              + ((lane>>4)*8)) * 2;

    const int nk = K / BK;
    LOAD_STAGE(0, 0);
    CP_COMMIT();

    for (int kt = 0; kt < nk; kt++) {
        if (kt + 1 < nk) {
            LOAD_STAGE((kt + 1) & 1, (kt + 1) * BK);
            CP_COMMIT();
            CP_WAIT1();
        } else {
            CP_WAIT0();
        }
        __syncthreads();

        unsigned stg = sbase + (kt & 1) * STG_B;
        #pragma unroll
        for (int kk = 0; kk < BK; kk += 16) {
            unsigned ah[4][4], bh[4][2];
            #pragma unroll
            for (int mf = 0; mf < 4; mf++) {
                unsigned ad = stg + aRowOff + (mf*16*SST + kk) * 2;
                LDSM4(ah[mf], ad);
            }
            #pragma unroll
            for (int nfp = 0; nfp < 2; nfp++) {
                unsigned r4[4];
                unsigned bd = stg + ARR_B + bRowOff + (nfp*16*SST + kk) * 2;
                LDSM4(r4, bd);
                bh[2*nfp][0]   = r4[0]; bh[2*nfp][1]   = r4[2];
                bh[2*nfp+1][0] = r4[1]; bh[2*nfp+1][1] = r4[3];
            }
            #pragma unroll
            for (int mf = 0; mf < 4; mf++)
                #pragma unroll
                for (int nf = 0; nf < 4; nf++)
                    MMAF16(acc[mf][nf], ah[mf], bh[nf]);
        }
        __syncthreads();
    }
#undef LOAD_STAGE

    // ---- epilogue ----
    #pragma unroll
    for (int mf = 0; mf < 4; mf++) {
        int m0 = bm + wm*64 + mf*16 + g;
        #pragma unroll
        for (int nf = 0; nf < 4; nf++) {
            int n0 = bn + wn*32 + nf*8 + t2;
            #pragma unroll
            for (int c = 0; c < 4; c++) {
                int m = m0 + (c >> 1) * 8;
                int n = n0 + (c & 1);
                if (n >= N) continue;
                float v = acc[mf][nf][c];
                if (bias) v += bias[n];
                if (flags & 1) v = 0.5f * v * (1.0f + erff(v * 0.70710678118654752f));
                v *= alpha;
                long o = (long)m * N + n;
                if (C) { if (flags & 2) C[o] += v; else C[o] = v; }
                if (Ch) Ch[o] = __float2half(v);
            }
        }
    }
}

// ---------------- flash attention v3 (fp16, cp.async) --------------------------
__global__ void __launch_bounds__(256)
k_attn_fa3()
{
    const int qt = (gridDim.x - 1) - blockIdx.x;
    const int h  = blockIdx.y, b = blockIdx.z;
    const int tid  = threadIdx.x;
    const int lane = tid & 31, warp = tid >> 5;
    const int wm = warp & 3, wn = warp >> 2;
    const int g  = lane >> 2;
    const int t2 = (lane & 3) * 2;

    extern __shared__ char dsm[];
    const unsigned sbase = (unsigned)__cvta_generic_to_shared(dsm);
    float* Omrg = (float*)dsm;
    __shared__ float sm_m[AQT], sm_l[AQT];

    const long rb3 = 3 * Dm;
    const int  t0  = qt * AQT;
    const long rowbase = (long)(b * Tn);

    // ---- stage Q (plain vector copies), load Q frags --------------------------
    #pragma unroll
    for (int j = 0; j < 2; j++) {
        int cid = tid + j * 256;
        int r = cid >> 3, q = (cid & 7) * 8;
        const __half* src = g_qkvh + (rowbase + t0 + r) * rb3 + h * HDm + q;
        *(uint4*)(dsm + (r * AST + q) * 2) = *(const uint4*)src;
    }
    __syncthreads();

    unsigned qh[4][4];
    const unsigned qRowOff = ((unsigned)(wm*16 + (lane&7) + ((lane>>3)&1)*8) * AST
                              + ((lane>>4)*8)) * 2;
    #pragma unroll
    for (int kk = 0; kk < 4; kk++) {
        unsigned qa = sbase + qRowOff + kk * 16 * 2;
        LDSM4(qh[kk], qa);
    }
    __syncthreads();

#define LOAD_KV(s, kt)                                                        \
    {                                                                         \
        unsigned st = sbase + (s) * ASTG;                                     \
        _Pragma("unroll")                                                     \
        for (int j = 0; j < 4; j++) {                                         \
            int cid = tid + j * 256;                                          \
            int arr = cid >> 9;                                               \
            int w = cid & 511;                                                \
            int r = w >> 3, q = (w & 7) * 8;                                  \
            long srow = (rowbase + (kt) * AKT + r) * rb3 + h * HDm + q        \
                        + (arr ? 2 * Dm : Dm);                                \
            cpa16(st + arr * AARR + (r * AST + q) * 2, g_qkvh + srow, 16);    \
        }                                                                     \
    }

    float oacc[8][4] = {};
    float mprev[2] = {-1e30f, -1e30f};
    float lsum [2] = {0.f, 0.f};

    const unsigned kRowOff = ((unsigned)(wn*32 + (lane&7) + ((lane>>3)&1)*8) * AST
                              + ((lane>>4)*8)) * 2;

    LOAD_KV(0, 0);
    CP_COMMIT();

    for (int kt = 0; kt <= qt; kt++) {
        if (kt < qt) {
            LOAD_KV((kt + 1) & 1, kt + 1);
            CP_COMMIT();
            CP_WAIT1();
        } else {
            CP_WAIT0();
        }
        __syncthreads();

        unsigned stg = sbase + (kt & 1) * ASTG;

        // ---- S = Q @ K^T ----
        float sacc[4][4] = {};
        #pragma unroll
        for (int kk = 0; kk < 4; kk++) {
            #pragma unroll
            for (int nfp = 0; nfp < 2; nfp++) {
                unsigned r4[4];
                unsigned kd = stg + kRowOff + (nfp*16*AST + kk*16) * 2;
                LDSM4(r4, kd);
                unsigned bh0[2] = {r4[0], r4[2]}, bh1[2] = {r4[1], r4[3]};
                MMAF16(sacc[2*nfp],   qh[kk], bh0);
                MMAF16(sacc[2*nfp+1], qh[kk], bh1);
            }
        }

        const bool diag = (kt == qt);
        #pragma unroll
        for (int nf = 0; nf < 4; nf++)
            #pragma unroll
            for (int c = 0; c < 4; c++) {
                float v = sacc[nf][c] * 0.125f;
                if (diag) {
                    int key = wn * 32 + nf * 8 + t2 + (c & 1);
                    int row = wm * 16 + g + (c >> 1) * 8;
                    if (key > row) v = -1.7e38f;
                }
                sacc[nf][c] = v;
            }

        // ---- online softmax ----
        float alpha[2];
        #pragma unroll
        for (int r = 0; r < 2; r++) {
            float rmax = -1.7e38f;
            #pragma unroll
            for (int nf = 0; nf < 4; nf++) {
                rmax = fmaxf(rmax, sacc[nf][2*r]);
                rmax = fmaxf(rmax, sacc[nf][2*r+1]);
            }
            rmax = fmaxf(rmax, __shfl_xor_sync(0xffffffffu, rmax, 1));
            rmax = fmaxf(rmax, __shfl_xor_sync(0xffffffffu, rmax, 2));
            float newm = fmaxf(mprev[r], rmax);
            alpha[r] = __expf(mprev[r] - newm);
            mprev[r] = newm;
            float ps = 0.f;
            #pragma unroll
            for (int nf = 0; nf < 4; nf++) {
                float p0 = __expf(sacc[nf][2*r]   - newm);
                float p1 = __expf(sacc[nf][2*r+1] - newm);
                sacc[nf][2*r] = p0; sacc[nf][2*r+1] = p1;
                ps += p0 + p1;
            }
            ps += __shfl_xor_sync(0xffffffffu, ps, 1);
            ps += __shfl_xor_sync(0xffffffffu, ps, 2);
            lsum[r] = lsum[r] * alpha[r] + ps;
        }
        #pragma unroll
        for (int nf = 0; nf < 8; nf++) {
            oacc[nf][0] *= alpha[0]; oacc[nf][1] *= alpha[0];
            oacc[nf][2] *= alpha[1]; oacc[nf][3] *= alpha[1];
        }

        // ---- O += P @ V  (V row-major, ldmatrix.trans) ----
        #pragma unroll
        for (int k2 = 0; k2 < 2; k2++) {
            unsigned pah[4];
            float* s0 = sacc[2*k2];
            float* s1 = sacc[2*k2+1];
            pah[0] = pack2h(s0[0], s0[1]);
            pah[1] = pack2h(s0[2], s0[3]);
            pah[2] = pack2h(s1[0], s1[1]);
            pah[3] = pack2h(s1[2], s1[3]);
            unsigned vRow = ((unsigned)(wn*32 + k2*16 + (lane&7) + ((lane>>3)&1)*8) * AST
                             + ((lane>>4)*8)) * 2;
            #pragma unroll
            for (int nfp = 0; nfp < 4; nfp++) {
                unsigned r4[4];
                unsigned vd = stg + AARR + vRow + nfp * 16 * 2;
                LDSM4T(r4, vd);
                unsigned vh0[2] = {r4[0], r4[1]}, vh1[2] = {r4[2], r4[3]};
                MMAF16(oacc[2*nfp],   pah, vh0);
                MMAF16(oacc[2*nfp+1], pah, vh1);
            }
        }
        __syncthreads();
    }
#undef LOAD_KV

    // ---- merge key-half warps, write fp16 output -------------------------------
    if (wn == 1) {
        #pragma unroll
        for (int nf = 0; nf < 8; nf++) {
            int d0 = nf * 8 + t2;
            Omrg[(wm*16 + g    ) * 64 + d0    ] = oacc[nf][0];
            Omrg[(wm*16 + g    ) * 64 + d0 + 1] = oacc[nf][1];
            Omrg[(wm*16 + g + 8) * 64 + d0    ] = oacc[nf][2];
            Omrg[(wm*16 + g + 8) * 64 + d0 + 1] = oacc[nf][3];
        }
        if ((lane & 3) == 0) {
            sm_m[wm*16 + g    ] = mprev[0];
            sm_m[wm*16 + g + 8] = mprev[1];
            sm_l[wm*16 + g    ] = lsum[0];
            sm_l[wm*16 + g + 8] = lsum[1];
        }
    }
    __syncthreads();
    if (wn == 0) {
        #pragma unroll
        for (int r = 0; r < 2; r++) {
            int rl = wm*16 + g + 8*r;
            float m1 = sm_m[rl], l1 = sm_l[rl];
            float m  = fmaxf(mprev[r], m1);
            float a0 = __expf(mprev[r] - m);
            float a1 = __expf(m1 - m);
            float inv = 1.0f / (lsum[r] * a0 + l1 * a1);
            long orow = ((long)(b * Tn + t0 + rl)) * Dm + h * HDm;
            #pragma unroll
            for (int nf = 0; nf < 8; nf++) {
                int d0 = nf * 8 + t2;
                float v0 = (oacc[nf][2*r]   * a0 + Omrg[rl*64 + d0    ] * a1) * inv;
                float v1 = (oacc[nf][2*r+1] * a0 + Omrg[rl*64 + d0 + 1] * a1) * inv;
                g_ath[orow + d0]     = __float2half(v0);
                g_ath[orow + d0 + 1] = __float2half(v1);
            }
        }
    }
}

// ---------------- residual add + LayerNorm (+ fp16 out) ------------------------
__global__ void k_add_ln(const float* __restrict__ x,
                         const float* __restrict__ y,
                         const float* __restrict__ g,
                         const float* __restrict__ bta,
                         float* __restrict__ out,
                         __half* __restrict__ oh)
{
    int row = blockIdx.x;
    int tid = threadIdx.x;
    __shared__ float buf[Dm];
    __shared__ float red[256];

    float psum = 0.f;
    for (int i = tid; i < Dm; i += 256) {
        float v = x[(long)row * Dm + i];
        if (y) v += y[(long)row * Dm + i];
        buf[i] = v;
        psum += v;
    }
    red[tid] = psum; __syncthreads();
    for (int s = 128; s > 0; s >>= 1) {
        if (tid < s) red[tid] += red[tid + s];
        __syncthreads();
    }
    float mu = red[0] * (1.0f / Dm); __syncthreads();

    float pvar = 0.f;
    for (int i = tid; i < Dm; i += 256) {
        float dv = buf[i] - mu;
        pvar += dv * dv;
    }
    red[tid] = pvar; __syncthreads();
    for (int s = 128; s > 0; s >>= 1) {
        if (tid < s) red[tid] += red[tid + s];
        __syncthreads();
    }
    float rstd = rsqrtf(red[0] * (1.0f / Dm) + EPSf); __syncthreads();

    for (int i = tid; i < Dm; i += 256) {
        float v = (buf[i] - mu) * rstd * g[i] + bta[i];
        long o = (long)row * Dm + i;
        out[o] = v;
        oh[o]  = __float2half(v);
    }
}

// ---------------- router -------------------------------------------------------
__global__ void k_router(const float* __restrict__ c_states,
                         const float* __restrict__ rw,
                         const float* __restrict__ rb, int layer)
{
    int tid = threadIdx.x;
    __shared__ float cm[CDm];
    __shared__ float lg[En];

    for (int d = tid; d < CDm; d += 256) {
        float s = 0.f;
        for (int r = 0; r < 64; r++) s += c_states[(long)r * CDm + d];
        cm[d] = s * (1.0f / 64.0f);
    }
    __syncthreads();
    if (tid < En) {
        float s = 0.f;
        const float* w = rw + (long)tid * CDm;
        for (int d = 0; d < CDm; d++) s += w[d] * cm[d];
        lg[tid] = s + rb[tid];
    }
    __syncthreads();
    if (tid == 0) {
        float mx = lg[0];
        for (int e = 1; e < En; e++) mx = fmaxf(mx, lg[e]);
        float p[En], sum = 0.f;
        for (int e = 0; e < En; e++) { p[e] = expf(lg[e] - mx); sum += p[e]; }
        for (int e = 0; e < En; e++) p[e] /= sum;
        int i0 = 0;
        for (int e = 1; e < En; e++) if (p[e] > p[i0]) i0 = e;
        int i1 = (i0 == 0) ? 1 : 0;
        for (int e = 0; e < En; e++) if (e != i0 && p[e] > p[i1]) i1 = e;
        float ws = p[i0] + p[i1];
        g_eidx2[layer*2 + 0] = i0; g_eidx2[layer*2 + 1] = i1;
        g_ew2[layer*2 + 0] = p[i0] / ws; g_ew2[layer*2 + 1] = p[i1] / ws;
    }
}

// ============================================================================
extern "C" void kernel_launch(void* const* d_in, const int* in_sizes, int n_in,
                              void* d_out, int out_size)
{
    const int*   tokens   = (const int*)  d_in[0];
    const float* c_states = (const float*)d_in[1];
    const float* embed_w  = (const float*)d_in[2];
    const float* pos_w    = (const float*)d_in[3];
    const float* in_w     = (const float*)d_in[4];
    const float* in_b     = (const float*)d_in[5];
    const float* out_w    = (const float*)d_in[6];
    const float* out_b    = (const float*)d_in[7];
    const float* ln_a_g   = (const float*)d_in[8];
    const float* ln_a_b   = (const float*)d_in[9];
    const float* router_w = (const float*)d_in[10];
    const float* router_b = (const float*)d_in[11];
    const float* e_w1     = (const float*)d_in[12];
    const float* e_b1     = (const float*)d_in[13];
    const float* e_w2     = (const float*)d_in[14];
    const float* e_b2     = (const float*)d_in[15];
    const float* ln_m_g   = (const float*)d_in[16];
    const float* ln_m_b   = (const float*)d_in[17];
    const float* ln_f_g   = (const float*)d_in[18];
    const float* ln_f_b   = (const float*)d_in[19];
    const float* head_w   = (const float*)d_in[20];
    float* out = (float*)d_out;

    cudaFuncSetAttribute(k_gemm3,    cudaFuncAttributeMaxDynamicSharedMemorySize, GEMM_SMEM);
    cudaFuncSetAttribute(k_attn_fa3, cudaFuncAttributeMaxDynamicSharedMemorySize, ATT_SMEM);

    float *p_x, *p_tmp, *p_moe, *p_xf;
    __half *p_xh,*p_qkvh,*p_ath,*p_hh,*p_xfh;
    __half *p_inwh,*p_outwh,*p_headh,*p_w1h,*p_w2h;
    cudaGetSymbolAddress((void**)&p_x,    g_x);
    cudaGetSymbolAddress((void**)&p_tmp,  g_tmp);
    cudaGetSymbolAddress((void**)&p_moe,  g_moe);
    cudaGetSymbolAddress((void**)&p_xf,   g_xf);
    cudaGetSymbolAddress((void**)&p_xh,   g_xh);
    cudaGetSymbolAddress((void**)&p_qkvh, g_qkvh);
    cudaGetSymbolAddress((void**)&p_ath,  g_ath);
    cudaGetSymbolAddress((void**)&p_hh,   g_hh);
    cudaGetSymbolAddress((void**)&p_xfh,  g_xfh);
    cudaGetSymbolAddress((void**)&p_inwh, g_inwh);
    cudaGetSymbolAddress((void**)&p_outwh,g_outwh);
    cudaGetSymbolAddress((void**)&p_headh,g_headh);
    cudaGetSymbolAddress((void**)&p_w1h,  g_w1h);
    cudaGetSymbolAddress((void**)&p_w2h,  g_w2h);

    // ---- routers (input-independent of x) ----
    for (int l = 0; l < Lnum; l++)
        k_router<<<1, 256>>>(c_states, router_w + (long)l * En * CDm,
                             router_b + (long)l * En, l);

    // ---- weight conversions ----
    {
        long n;
        n = (long)Lnum * 3 * Dm * Dm;
        k_half<<<(unsigned)((n/4 + 255) / 256), 256>>>(in_w, p_inwh, n);
        n = (long)Lnum * Dm * Dm;
        k_half<<<(unsigned)((n/4 + 255) / 256), 256>>>(out_w, p_outwh, n);
        n = (long)Vv * Dm;
        k_half<<<(unsigned)((n/4 + 255) / 256), 256>>>(head_w, p_headh, n);
        long ne = (long)Fm * Dm;
        unsigned ge = (unsigned)((ne/4 + 255) / 256);
        for (int l = 0; l < Lnum; l++)
            for (int s = 0; s < 2; s++) {
                int sidx = l*2 + s;
                k_half_exp<<<ge, 256>>>(e_w1 + (long)l * En * Fm * Dm,
                                        p_w1h + (long)sidx * ne, ne, sidx);
                k_half_exp<<<ge, 256>>>(e_w2 + (long)l * En * Dm * Fm,
                                        p_w2h + (long)sidx * ne, ne, sidx);
            }
    }

    k_embed<<<BT, 256>>>(tokens, embed_w, pos_w);

    dim3 blk(256);
    for (int l = 0; l < Lnum; l++) {
        {   // QKV projection -> fp16 qkv
            dim3 grid((3 * Dm) / BN, BT / BM);
            k_gemm3<<<grid, blk, GEMM_SMEM>>>(
                p_xh, p_inwh + (long)l * 3 * Dm * Dm,
                in_b + (long)l * 3 * Dm,
                nullptr, p_qkvh,
                BT, 3 * Dm, Dm, 0, 0);
        }
        {   // flash attention -> fp16 attn
            dim3 grid(Tn / AQT, Hn, Bn);
            k_attn_fa3<<<grid, 256, ATT_SMEM>>>();
        }
        {   // output projection -> fp32 tmp
            dim3 grid(Dm / BN, BT / BM);
            k_gemm3<<<grid, blk, GEMM_SMEM>>>(
                p_ath, p_outwh + (long)l * Dm * Dm,
                out_b + (long)l * Dm,
                p_tmp, nullptr,
                BT, Dm, Dm, 0, 0);
        }
        k_add_ln<<<BT, 256>>>(p_x, p_tmp, ln_a_g + l * Dm, ln_a_b + l * Dm,
                              p_x, p_xh);

        for (int s = 0; s < 2; s++) {
            int sidx = l*2 + s;
            long ne = (long)Fm * Dm;
            {   // expert W1: GELU -> fp16 h
                dim3 grid(Fm / BN, BT / BM);
                k_gemm3<<<grid, blk, GEMM_SMEM>>>(
                    p_xh, p_w1h + (long)sidx * ne,
                    e_b1 + (long)l * En * Fm,
                    nullptr, p_hh,
                    BT, Fm, Dm, sidx, 1 | 8);
            }
            {   // expert W2: scale (+accum) -> fp32 moe
                dim3 grid(Dm / BN, BT / BM);
                int flags = 4 | 8 | (s == 1 ? 2 : 0);
                k_gemm3<<<grid, blk, GEMM_SMEM>>>(
                    p_hh, p_w2h + (long)sidx * ne,
                    e_b2 + (long)l * En * Dm,
                    p_moe, nullptr,
                    BT, Dm, Fm, sidx, flags);
            }
        }
        k_add_ln<<<BT, 256>>>(p_x, p_moe, ln_m_g + l * Dm, ln_m_b + l * Dm,
                              p_x, p_xh);
    }

    k_add_ln<<<BT, 256>>>(p_x, nullptr, ln_f_g, ln_f_b, p_xf, p_xfh);

    {   // LM head
        dim3 grid((Vv + BN - 1) / BN, BT / BM);
        k_gemm3<<<grid, blk, GEMM_SMEM>>>(
            p_xfh, p_headh, nullptr,
            out, nullptr,
            BT, Vv, Dm, 0, 0);
    }
}